// round 12
// baseline (speedup 1.0000x reference)
#include <cuda_runtime.h>
#include <cuda_fp16.h>
#include <math.h>

#define NN 8192
#define NE 262144
#define CS 384
#define CZ 128
#define CH 16
#define HH 12
#define PQK 4
#define PV 8
#define PROJ_COLS 1152      // 192 q | 384 kv | 144 qp | 432 kvp
#define EDGE_COLS 44        // 12 b | 32 pz
#define FEAT_COLS 960
#define S_QK 0.14433756729740643f
#define S_B  0.5773502691896258f
#define S_PT 0.1360827634879543f
#define INF_C 100000.0f
#define DN_FAST 128

// ---------------- scratch ----------------
__device__ float  g_proj[(size_t)NN * PROJ_COLS];
__device__ float  g_qpts[(size_t)NN * 144];
__device__ float  g_kpts[(size_t)NN * 144];
__device__ __half g_k16[(size_t)NN * 192];
__device__ __half g_v16[(size_t)NN * 192];
__device__ __half g_vpts16[(size_t)NN * 288];
__device__ __half g_pz16[(size_t)NE * 32];
__device__ float  g_bE[(size_t)NE * 12];
__device__ float  g_abuf[(size_t)NE * HH];
__device__ __align__(16) __half g_feats16[(size_t)NN * FEAT_COLS];
__device__ int    g_rank[NE];
__device__ int    g_dstOf[NE];
__device__ int    g_hist[NN];
__device__ int    g_off[NN + 1];
__device__ int    g_cursor[NN];
__device__ unsigned g_Wp16[(CS / 2) * PROJ_COLS];
__device__ unsigned g_We16[(CZ / 2) * EDGE_COLS];
__device__ unsigned g_Wo16[(FEAT_COLS / 2) * CS];
__device__ float    g_Bproj[PROJ_COLS];
__device__ float    g_Bedge[EDGE_COLS];

__device__ __forceinline__ unsigned pack_h2(float x, float y) {
    __half2 h = __floats2half2_rn(x, y);
    return *reinterpret_cast<unsigned*>(&h);
}

// ---------------- weight packing ----------------
#define SEG0 ((CS / 2) * PROJ_COLS)
#define SEG1 ((CZ / 2) * EDGE_COLS)
#define SEG2 ((FEAT_COLS / 2) * CS)
#define PACKP_TOTAL (SEG0 + PROJ_COLS)
#define PACKR_TOTAL (SEG1 + SEG2 + EDGE_COLS)

__device__ __forceinline__ float projw(int k, int col,
                                       const float* q_w, const float* kv_w,
                                       const float* qp_w, const float* kvp_w) {
    if (col < 192)  return q_w[k * 192 + col];
    if (col < 576)  return kv_w[k * 384 + (col - 192)];
    if (col < 720)  return qp_w[k * 144 + (col - 576)];
    return kvp_w[k * 432 + (col - 720)];
}

__global__ void k_pack_proj(const float* __restrict__ q_w, const float* __restrict__ q_b,
                            const float* __restrict__ kv_w, const float* __restrict__ kv_b,
                            const float* __restrict__ qp_w, const float* __restrict__ qp_b,
                            const float* __restrict__ kvp_w, const float* __restrict__ kvp_b) {
    int gid = blockIdx.x * blockDim.x + threadIdx.x;
    if (gid < SEG0) {
        int r2 = gid / PROJ_COLS, col = gid % PROJ_COLS;
        g_Wp16[gid] = pack_h2(projw(2 * r2, col, q_w, kv_w, qp_w, kvp_w),
                              projw(2 * r2 + 1, col, q_w, kv_w, qp_w, kvp_w));
    } else if (gid < PACKP_TOTAL) {
        int j = gid - SEG0;
        float v;
        if (j < 192)      v = q_b[j];
        else if (j < 576) v = kv_b[j - 192];
        else if (j < 720) v = qp_b[j - 576];
        else              v = kvp_b[j - 720];
        g_Bproj[j] = v;
    }
}

__global__ void k_pack_rest(const float* __restrict__ b_w, const float* __restrict__ b_b,
                            const float* __restrict__ dz_w, const float* __restrict__ dz_b,
                            const float* __restrict__ out_w) {
    int gid = blockIdx.x * blockDim.x + threadIdx.x;
    if (gid < SEG1) {
        int r2 = gid / EDGE_COLS, c = gid % EDGE_COLS;
        float v0 = (c < 12) ? b_w[(2 * r2) * 12 + c] : dz_w[(2 * r2) * 32 + (c - 12)];
        float v1 = (c < 12) ? b_w[(2 * r2 + 1) * 12 + c] : dz_w[(2 * r2 + 1) * 32 + (c - 12)];
        g_We16[gid] = pack_h2(v0, v1);
    } else if (gid < SEG1 + SEG2) {
        int j = gid - SEG1;
        int r2 = j / CS, c = j % CS;
        g_Wo16[j] = pack_h2(out_w[(size_t)(2 * r2) * CS + c],
                            out_w[(size_t)(2 * r2 + 1) * CS + c]);
    } else if (gid < PACKR_TOTAL) {
        int c = gid - SEG1 - SEG2;
        g_Bedge[c] = (c < 12) ? b_b[c] : dz_b[c - 12];
    }
}

// ---------------- sorting ----------------
__global__ void k_zero_hist() {
    int i = blockIdx.x * blockDim.x + threadIdx.x;
    if (i < NN) g_hist[i] = 0;
}
__global__ void k_hist(const int* __restrict__ edge_index) {
    int e = blockIdx.x * blockDim.x + threadIdx.x;
    if (e < NE) atomicAdd(&g_hist[edge_index[NE + e]], 1);
}
__global__ void k_scan() {
    __shared__ int wsum[32];
    int tid = threadIdx.x;
    int lane = tid & 31, wid = tid >> 5;
    int base = tid * 8;
    int local[8];
    int s = 0;
    #pragma unroll
    for (int i = 0; i < 8; i++) { local[i] = g_hist[base + i]; s += local[i]; }
    int v = s;
    #pragma unroll
    for (int d = 1; d < 32; d <<= 1) {
        int t = __shfl_up_sync(0xffffffffu, v, d);
        if (lane >= d) v += t;
    }
    if (lane == 31) wsum[wid] = v;
    __syncthreads();
    if (wid == 0) {
        int w = wsum[lane];
        #pragma unroll
        for (int d = 1; d < 32; d <<= 1) {
            int t = __shfl_up_sync(0xffffffffu, w, d);
            if (lane >= d) w += t;
        }
        wsum[lane] = w;
    }
    __syncthreads();
    int run = v - s + (wid > 0 ? wsum[wid - 1] : 0);
    #pragma unroll
    for (int i = 0; i < 8; i++) {
        g_off[base + i] = run;
        g_cursor[base + i] = run;
        run += local[i];
    }
    if (tid == 1023) g_off[NN] = run;
}
__global__ void k_scatter(const int* __restrict__ edge_index) {
    int e = blockIdx.x * blockDim.x + threadIdx.x;
    if (e >= NE) return;
    int src = edge_index[NE + e];
    int dst = edge_index[e];
    int pos = atomicAdd(&g_cursor[src], 1);
    g_rank[e] = pos;
    g_dstOf[pos] = dst;
}

// ---------------- fp16 mma helper ----------------
__device__ __forceinline__ void mma_f16(float* c, unsigned a0, unsigned a1, unsigned a2,
                                        unsigned a3, unsigned b0, unsigned b1) {
    asm volatile("mma.sync.aligned.m16n8k16.row.col.f32.f16.f16.f32 "
                 "{%0,%1,%2,%3}, {%4,%5,%6,%7}, {%8,%9}, {%0,%1,%2,%3};"
                 : "+f"(c[0]), "+f"(c[1]), "+f"(c[2]), "+f"(c[3])
                 : "r"(a0), "r"(a1), "r"(a2), "r"(a3), "r"(b0), "r"(b1));
}

#define AP2 136
#define BP2 136
#define EBP2 72
#define SMEM_ARENA 17408

__device__ __forceinline__ void proj_store2(int r, int col, float v0, float v1) {
    if (col >= 192 && col < 576) {
        int u = col - 192;
        int h = u >> 5, c = u & 31;
        __half2 hv = __floats2half2_rn(v0, v1);
        if (c < 16) *reinterpret_cast<__half2*>(&g_k16[(size_t)r * 192 + h * 16 + c]) = hv;
        else        *reinterpret_cast<__half2*>(&g_v16[(size_t)r * 192 + h * 16 + (c - 16)]) = hv;
    } else {
        float2 fv = make_float2(v0, v1);
        *reinterpret_cast<float2*>(&g_proj[(size_t)r * PROJ_COLS + col]) = fv;
    }
}

// ---------------- pipelined 128x128 fp16 GEMM (proj) ----------------
template <int N, int K, int MODE>
__device__ __forceinline__ void gemm128_f16(const void* __restrict__ Aptr,
                                            const unsigned* __restrict__ W16,
                                            const float* __restrict__ Bias,
                                            float* __restrict__ C,
                                            int row0, int col0, char* smemraw) {
    unsigned (*As)[8][AP2] = reinterpret_cast<unsigned (*)[8][AP2]>(smemraw);
    unsigned (*Bs)[8][BP2] = reinterpret_cast<unsigned (*)[8][BP2]>(smemraw + 2 * 8 * AP2 * 4);
    const float* Af = (const float*)Aptr;
    const int tid = threadIdx.x;
    const int lane = tid & 31, w = tid >> 5;
    const int gid = lane >> 2, tig = lane & 3;
    const int wm = (w & 1) * 64;
    const int wn = (w >> 1) * 32;

    float acc[4][4][4];
    #pragma unroll
    for (int mt = 0; mt < 4; mt++)
        #pragma unroll
        for (int nt = 0; nt < 4; nt++)
            #pragma unroll
            for (int i = 0; i < 4; i++) acc[mt][nt][i] = 0.f;

    float4 pa[2];
    unsigned pb[4];

    #pragma unroll
    for (int l = 0; l < 2; l++) {
        int idx = tid + 256 * l;
        int m = idx >> 2, kq = (idx & 3) * 4;
        pa[l] = *reinterpret_cast<const float4*>(&Af[(size_t)(row0 + m) * K + kq]);
    }
    #pragma unroll
    for (int l = 0; l < 4; l++) {
        int idx = tid + 256 * l;
        int r = idx >> 7, c = idx & 127;
        pb[l] = W16[(size_t)r * N + col0 + c];
    }
    #pragma unroll
    for (int l = 0; l < 2; l++) {
        int idx = tid + 256 * l;
        int m = idx >> 2, k2 = (idx & 3) * 2;
        As[0][k2 + 0][m] = pack_h2(pa[l].x, pa[l].y);
        As[0][k2 + 1][m] = pack_h2(pa[l].z, pa[l].w);
    }
    #pragma unroll
    for (int l = 0; l < 4; l++) {
        int idx = tid + 256 * l;
        Bs[0][idx >> 7][idx & 127] = pb[l];
    }
    __syncthreads();

    const int nIter = K / 16;
    for (int it = 0; it < nIter; it++) {
        int buf = it & 1;
        if (it + 1 < nIter) {
            int k0 = (it + 1) * 16;
            #pragma unroll
            for (int l = 0; l < 2; l++) {
                int idx = tid + 256 * l;
                int m = idx >> 2, kq = (idx & 3) * 4;
                pa[l] = *reinterpret_cast<const float4*>(&Af[(size_t)(row0 + m) * K + k0 + kq]);
            }
            #pragma unroll
            for (int l = 0; l < 4; l++) {
                int idx = tid + 256 * l;
                int r = idx >> 7, c = idx & 127;
                pb[l] = W16[(size_t)(k0 / 2 + r) * N + col0 + c];
            }
        }
        {
            unsigned a[4][4], b[4][2];
            #pragma unroll
            for (int mt = 0; mt < 4; mt++) {
                int m0 = wm + mt * 16;
                a[mt][0] = As[buf][tig][m0 + gid];
                a[mt][1] = As[buf][tig][m0 + gid + 8];
                a[mt][2] = As[buf][tig + 4][m0 + gid];
                a[mt][3] = As[buf][tig + 4][m0 + gid + 8];
            }
            #pragma unroll
            for (int nt = 0; nt < 4; nt++) {
                int n0 = wn + nt * 8;
                b[nt][0] = Bs[buf][tig][n0 + gid];
                b[nt][1] = Bs[buf][tig + 4][n0 + gid];
            }
            #pragma unroll
            for (int mt = 0; mt < 4; mt++)
                #pragma unroll
                for (int nt = 0; nt < 4; nt++)
                    mma_f16(acc[mt][nt], a[mt][0], a[mt][1], a[mt][2], a[mt][3],
                            b[nt][0], b[nt][1]);
        }
        if (it + 1 < nIter) {
            int nb = 1 - buf;
            #pragma unroll
            for (int l = 0; l < 2; l++) {
                int idx = tid + 256 * l;
                int m = idx >> 2, k2 = (idx & 3) * 2;
                As[nb][k2 + 0][m] = pack_h2(pa[l].x, pa[l].y);
                As[nb][k2 + 1][m] = pack_h2(pa[l].z, pa[l].w);
            }
            #pragma unroll
            for (int l = 0; l < 4; l++) {
                int idx = tid + 256 * l;
                Bs[nb][idx >> 7][idx & 127] = pb[l];
            }
        }
        __syncthreads();
    }
    #pragma unroll
    for (int mt = 0; mt < 4; mt++) {
        #pragma unroll
        for (int i = 0; i < 2; i++) {
            int r = row0 + wm + mt * 16 + gid + i * 8;
            #pragma unroll
            for (int nt = 0; nt < 4; nt++) {
                int cb = col0 + wn + nt * 8 + 2 * tig;
                float v0 = acc[mt][nt][i * 2 + 0] + Bias[cb + 0];
                float v1 = acc[mt][nt][i * 2 + 1] + Bias[cb + 1];
                if (MODE == 1) proj_store2(r, cb, v0, v1);
                else {
                    C[(size_t)r * N + cb]     = v0;
                    C[(size_t)r * N + cb + 1] = v1;
                }
            }
        }
    }
}

// ---------------- pipelined 64x128 fp16 GEMM (out; half A) ----------------
template <int N, int K>
__device__ __forceinline__ void gemm64_f16h(const __half* __restrict__ Ah,
                                            const unsigned* __restrict__ W16,
                                            const float* __restrict__ Bias,
                                            float* __restrict__ C,
                                            int row0, int col0, char* smemraw) {
    unsigned (*As)[8][AP2] = reinterpret_cast<unsigned (*)[8][AP2]>(smemraw);
    unsigned (*Bs)[8][BP2] = reinterpret_cast<unsigned (*)[8][BP2]>(smemraw + 2 * 8 * AP2 * 4);
    const int tid = threadIdx.x;
    const int lane = tid & 31, w = tid >> 5;
    const int gid = lane >> 2, tig = lane & 3;
    const int wm = (w & 1) * 32;
    const int wn = (w >> 1) * 32;

    float acc[2][4][4];
    #pragma unroll
    for (int mt = 0; mt < 2; mt++)
        #pragma unroll
        for (int nt = 0; nt < 4; nt++)
            #pragma unroll
            for (int i = 0; i < 4; i++) acc[mt][nt][i] = 0.f;

    uint2 pah;
    unsigned pb[4];

    {
        int m = tid >> 2, k4 = (tid & 3) * 4;
        pah = *reinterpret_cast<const uint2*>(&Ah[(size_t)(row0 + m) * K + k4]);
    }
    #pragma unroll
    for (int l = 0; l < 4; l++) {
        int idx = tid + 256 * l;
        int r = idx >> 7, c = idx & 127;
        pb[l] = W16[(size_t)r * N + col0 + c];
    }
    {
        int m = tid >> 2, k2 = (tid & 3) * 2;
        As[0][k2 + 0][m] = pah.x;
        As[0][k2 + 1][m] = pah.y;
    }
    #pragma unroll
    for (int l = 0; l < 4; l++) {
        int idx = tid + 256 * l;
        Bs[0][idx >> 7][idx & 127] = pb[l];
    }
    __syncthreads();

    const int nIter = K / 16;
    for (int it = 0; it < nIter; it++) {
        int buf = it & 1;
        if (it + 1 < nIter) {
            int k0 = (it + 1) * 16;
            int m = tid >> 2, k4 = (tid & 3) * 4;
            pah = *reinterpret_cast<const uint2*>(&Ah[(size_t)(row0 + m) * K + k0 + k4]);
            #pragma unroll
            for (int l = 0; l < 4; l++) {
                int idx = tid + 256 * l;
                int r = idx >> 7, c = idx & 127;
                pb[l] = W16[(size_t)(k0 / 2 + r) * N + col0 + c];
            }
        }
        {
            unsigned a[2][4], b[4][2];
            #pragma unroll
            for (int mt = 0; mt < 2; mt++) {
                int m0 = wm + mt * 16;
                a[mt][0] = As[buf][tig][m0 + gid];
                a[mt][1] = As[buf][tig][m0 + gid + 8];
                a[mt][2] = As[buf][tig + 4][m0 + gid];
                a[mt][3] = As[buf][tig + 4][m0 + gid + 8];
            }
            #pragma unroll
            for (int nt = 0; nt < 4; nt++) {
                int n0 = wn + nt * 8;
                b[nt][0] = Bs[buf][tig][n0 + gid];
                b[nt][1] = Bs[buf][tig + 4][n0 + gid];
            }
            #pragma unroll
            for (int mt = 0; mt < 2; mt++)
                #pragma unroll
                for (int nt = 0; nt < 4; nt++)
                    mma_f16(acc[mt][nt], a[mt][0], a[mt][1], a[mt][2], a[mt][3],
                            b[nt][0], b[nt][1]);
        }
        if (it + 1 < nIter) {
            int nb = 1 - buf;
            int m = tid >> 2, k2 = (tid & 3) * 2;
            As[nb][k2 + 0][m] = pah.x;
            As[nb][k2 + 1][m] = pah.y;
            #pragma unroll
            for (int l = 0; l < 4; l++) {
                int idx = tid + 256 * l;
                Bs[nb][idx >> 7][idx & 127] = pb[l];
            }
        }
        __syncthreads();
    }
    #pragma unroll
    for (int mt = 0; mt < 2; mt++) {
        #pragma unroll
        for (int i = 0; i < 2; i++) {
            int r = row0 + wm + mt * 16 + gid + i * 8;
            #pragma unroll
            for (int nt = 0; nt < 4; nt++) {
                int cb = col0 + wn + nt * 8 + 2 * tig;
                C[(size_t)r * N + cb]     = acc[mt][nt][i * 2 + 0] + Bias[cb + 0];
                C[(size_t)r * N + cb + 1] = acc[mt][nt][i * 2 + 1] + Bias[cb + 1];
            }
        }
    }
}

// ---------------- pipelined 128x64 fp16 edge GEMM ----------------
__device__ __forceinline__ void edge_gemm_f16(const float* __restrict__ A,
                                              const unsigned* __restrict__ W16,
                                              const float* __restrict__ Bias,
                                              const int* __restrict__ rowmap,
                                              int row0, char* smemraw) {
    unsigned (*As)[8][AP2] = reinterpret_cast<unsigned (*)[8][AP2]>(smemraw);
    unsigned (*Bs)[8][EBP2] = reinterpret_cast<unsigned (*)[8][EBP2]>(smemraw + 2 * 8 * AP2 * 4);
    const int tid = threadIdx.x;
    const int lane = tid & 31, w = tid >> 5;
    const int gid = lane >> 2, tig = lane & 3;
    const int wm = (w & 3) * 32;
    const int wn = (w >> 2) * 32;
    const int N = EDGE_COLS, K = CZ;

    float c[2][4][4];
    #pragma unroll
    for (int mt = 0; mt < 2; mt++)
        #pragma unroll
        for (int nt = 0; nt < 4; nt++)
            #pragma unroll
            for (int i = 0; i < 4; i++) c[mt][nt][i] = 0.f;

    float4 pa[2];
    unsigned pb[2];

    #pragma unroll
    for (int l = 0; l < 2; l++) {
        int idx = tid + 256 * l;
        int r = idx >> 2, kc = (idx & 3) * 4;
        pa[l] = *reinterpret_cast<const float4*>(&A[(size_t)(row0 + r) * K + kc]);
    }
    #pragma unroll
    for (int l = 0; l < 2; l++) {
        int idx = tid + 256 * l;
        int r = idx >> 6, cc = idx & 63;
        pb[l] = (cc < N) ? W16[(size_t)r * N + cc] : 0u;
    }
    #pragma unroll
    for (int l = 0; l < 2; l++) {
        int idx = tid + 256 * l;
        int r = idx >> 2, k2 = (idx & 3) * 2;
        As[0][k2 + 0][r] = pack_h2(pa[l].x, pa[l].y);
        As[0][k2 + 1][r] = pack_h2(pa[l].z, pa[l].w);
    }
    #pragma unroll
    for (int l = 0; l < 2; l++) {
        int idx = tid + 256 * l;
        Bs[0][idx >> 6][idx & 63] = pb[l];
    }
    __syncthreads();

    const int nIter = K / 16;
    for (int it = 0; it < nIter; it++) {
        int buf = it & 1;
        if (it + 1 < nIter) {
            int k0 = (it + 1) * 16;
            #pragma unroll
            for (int l = 0; l < 2; l++) {
                int idx = tid + 256 * l;
                int r = idx >> 2, kc = (idx & 3) * 4;
                pa[l] = *reinterpret_cast<const float4*>(&A[(size_t)(row0 + r) * K + k0 + kc]);
            }
            #pragma unroll
            for (int l = 0; l < 2; l++) {
                int idx = tid + 256 * l;
                int r = idx >> 6, cc = idx & 63;
                pb[l] = (cc < N) ? W16[(size_t)(k0 / 2 + r) * N + cc] : 0u;
            }
        }
        {
            unsigned a[2][4], b[4][2];
            #pragma unroll
            for (int mt = 0; mt < 2; mt++) {
                int m0 = wm + mt * 16;
                a[mt][0] = As[buf][tig][m0 + gid];
                a[mt][1] = As[buf][tig][m0 + gid + 8];
                a[mt][2] = As[buf][tig + 4][m0 + gid];
                a[mt][3] = As[buf][tig + 4][m0 + gid + 8];
            }
            #pragma unroll
            for (int nt = 0; nt < 4; nt++) {
                int n0 = wn + nt * 8;
                b[nt][0] = Bs[buf][tig][n0 + gid];
                b[nt][1] = Bs[buf][tig + 4][n0 + gid];
            }
            #pragma unroll
            for (int mt = 0; mt < 2; mt++)
                #pragma unroll
                for (int nt = 0; nt < 4; nt++)
                    mma_f16(c[mt][nt], a[mt][0], a[mt][1], a[mt][2], a[mt][3],
                            b[nt][0], b[nt][1]);
        }
        if (it + 1 < nIter) {
            int nb = 1 - buf;
            #pragma unroll
            for (int l = 0; l < 2; l++) {
                int idx = tid + 256 * l;
                int r = idx >> 2, k2 = (idx & 3) * 2;
                As[nb][k2 + 0][r] = pack_h2(pa[l].x, pa[l].y);
                As[nb][k2 + 1][r] = pack_h2(pa[l].z, pa[l].w);
            }
            #pragma unroll
            for (int l = 0; l < 2; l++) {
                int idx = tid + 256 * l;
                Bs[nb][idx >> 6][idx & 63] = pb[l];
            }
        }
        __syncthreads();
    }
    #pragma unroll
    for (int mt = 0; mt < 2; mt++) {
        #pragma unroll
        for (int i = 0; i < 2; i++) {
            int r = row0 + wm + mt * 16 + gid + i * 8;
            int crow = rowmap[r];
            #pragma unroll
            for (int nt = 0; nt < 4; nt++) {
                int cbase = wn + nt * 8 + 2 * tig;
                #pragma unroll
                for (int j = 0; j < 2; j++) {
                    int cc = cbase + j;
                    if (cc < N) {
                        float val = c[mt][nt][i * 2 + j] + Bias[cc];
                        if (cc < 12) g_bE[(size_t)crow * 12 + cc] = val;
                        else         g_pz16[(size_t)crow * 32 + (cc - 12)] = __float2half(val);
                    }
                }
            }
        }
    }
}

__global__ __launch_bounds__(256, 2) void k_gemm_proj(const float* __restrict__ s) {
    __shared__ __align__(16) char smemraw[SMEM_ARENA];
    int b = blockIdx.x;
    gemm128_f16<PROJ_COLS, CS, 1>(s, g_Wp16, g_Bproj, nullptr,
                                  (b / 9) * 128, (b % 9) * 128, smemraw);
}
__global__ __launch_bounds__(256, 2) void k_gemm_edge(const float* __restrict__ z) {
    __shared__ __align__(16) char smemraw[SMEM_ARENA];
    edge_gemm_f16(z, g_We16, g_Bedge, g_rank, blockIdx.x * 128, smemraw);
}
__global__ __launch_bounds__(256, 2) void k_gemm_out(const float* __restrict__ out_b,
                                                     float* __restrict__ out) {
    __shared__ __align__(16) char smemraw[SMEM_ARENA];
    gemm64_f16h<CS, FEAT_COLS>(g_feats16, g_Wo16, out_b, out,
                               blockIdx.y * 64, blockIdx.x * 128, smemraw);
}

// ---------------- point transform ----------------
__global__ void k_pointify(const float* __restrict__ rot, const float* __restrict__ trans) {
    int gid = blockIdx.x * blockDim.x + threadIdx.x;
    if (gid >= NN * 192) return;
    int n = gid / 192;
    int p_all = gid % 192;
    const float* R = rot + (size_t)n * 9;
    const float* T = trans + (size_t)n * 3;
    const float* pr = g_proj + (size_t)n * PROJ_COLS;
    if (p_all < 48) {
        int p = p_all;
        float y0 = pr[576 + 0 * 48 + p];
        float y1 = pr[576 + 1 * 48 + p];
        float y2 = pr[576 + 2 * 48 + p];
        #pragma unroll
        for (int i = 0; i < 3; i++) {
            float v = R[i * 3 + 0] * y0 + R[i * 3 + 1] * y1 + R[i * 3 + 2] * y2 + T[i];
            g_qpts[((size_t)n * 48 + p) * 3 + i] = v;
        }
    } else {
        int p = p_all - 48;
        float y0 = pr[720 + 0 * 144 + p];
        float y1 = pr[720 + 1 * 144 + p];
        float y2 = pr[720 + 2 * 144 + p];
        int h = p / 12, j = p % 12;
        #pragma unroll
        for (int i = 0; i < 3; i++) {
            float v = R[i * 3 + 0] * y0 + R[i * 3 + 1] * y1 + R[i * 3 + 2] * y2 + T[i];
            if (j < PQK) g_kpts[((size_t)n * 48 + h * 4 + j) * 3 + i] = v;
            else         g_vpts16[(size_t)n * 288 + (h * 8 + (j - 4)) * 3 + i] = __float2half(v);
        }
    }
}

// ---------------- fused per-node: logits + softmax + aggregation ----------------
__device__ __forceinline__ float4 h4_to_f4(uint2 u) {
    __half2* hp = reinterpret_cast<__half2*>(&u);
    float2 f0 = __half22float2(hp[0]);
    float2 f1 = __half22float2(hp[1]);
    return make_float4(f0.x, f0.y, f1.x, f1.y);
}

template <bool FAST>
__device__ __forceinline__ void node_body(
    int n, int tid, int beg, int dn,
    const float* __restrict__ mask, const float* __restrict__ head_weights,
    const float* __restrict__ rot, const float* __restrict__ trans,
    float4* s_q, float4* s_qp, float* s_hw, float* s_logit, int* s_dst,
    float* s_red, float* s_amax, float* s_inv, float* sacc, float* s_pt2) {

    const float4* proj4 = reinterpret_cast<const float4*>(g_proj);
    const float4* kpts4 = reinterpret_cast<const float4*>(g_kpts);

    float* lb = FAST ? s_logit : (g_abuf + (size_t)beg * HH);
    const int* dl = FAST ? s_dst : (g_dstOf + beg);

    if (tid < 48) s_q[tid] = proj4[(size_t)n * 288 + tid];
    else if (tid < 84) s_qp[tid - 48] = reinterpret_cast<const float4*>(g_qpts)[(size_t)n * 36 + (tid - 48)];
    else if (tid < 96) s_hw[tid - 84] = 0.5f * S_PT * log1pf(expf(head_weights[tid - 84]));
    if (FAST) {
        for (int i = tid; i < dn; i += 256) s_dst[i] = g_dstOf[beg + i];
    }
    __syncthreads();

    float mn = mask[n];

    if (tid < 252) {
        int h = tid % HH;
        float4 q0 = s_q[h * 4 + 0], q1 = s_q[h * 4 + 1], q2 = s_q[h * 4 + 2], q3 = s_q[h * 4 + 3];
        float4 p0 = s_qp[h * 3 + 0], p1 = s_qp[h * 3 + 1], p2 = s_qp[h * 3 + 2];
        float hwv = s_hw[h];
        for (int i = tid / HH; i < dn; i += 21) {
            int dst = dl[i];
            const uint4* kh = reinterpret_cast<const uint4*>(g_k16 + (size_t)dst * 192 + h * 16);
            uint4 u0 = kh[0], u1 = kh[1];
            __half2* h0 = reinterpret_cast<__half2*>(&u0);
            __half2* h1 = reinterpret_cast<__half2*>(&u1);
            float2 f0 = __half22float2(h0[0]), f1 = __half22float2(h0[1]);
            float2 f2 = __half22float2(h0[2]), f3 = __half22float2(h0[3]);
            float2 f4 = __half22float2(h1[0]), f5 = __half22float2(h1[1]);
            float2 f6 = __half22float2(h1[2]), f7 = __half22float2(h1[3]);
            float dot = q0.x * f0.x + q0.y * f0.y + q0.z * f1.x + q0.w * f1.y
                      + q1.x * f2.x + q1.y * f2.y + q1.z * f3.x + q1.w * f3.y
                      + q2.x * f4.x + q2.y * f4.y + q2.z * f5.x + q2.w * f5.y
                      + q3.x * f6.x + q3.y * f6.y + q3.z * f7.x + q3.w * f7.y;
            const float4* kp = kpts4 + (size_t)dst * 36 + h * 3;
            float4 d0 = kp[0], d1 = kp[1], d2 = kp[2];
            float pt = 0.f;
            pt += (p0.x - d0.x) * (p0.x - d0.x) + (p0.y - d0.y) * (p0.y - d0.y)
                + (p0.z - d0.z) * (p0.z - d0.z) + (p0.w - d0.w) * (p0.w - d0.w);
            pt += (p1.x - d1.x) * (p1.x - d1.x) + (p1.y - d1.y) * (p1.y - d1.y)
                + (p1.z - d1.z) * (p1.z - d1.z) + (p1.w - d1.w) * (p1.w - d1.w);
            pt += (p2.x - d2.x) * (p2.x - d2.x) + (p2.y - d2.y) * (p2.y - d2.y)
                + (p2.z - d2.z) * (p2.z - d2.z) + (p2.w - d2.w) * (p2.w - d2.w);
            float b = g_bE[(size_t)(beg + i) * 12 + h];
            float em = INF_C * (mask[dst] * mn - 1.f);
            lb[i * HH + h] = dot * S_QK + S_B * b - hwv * pt + em;
        }
    }
    __syncthreads();

    if (tid < 96) {
        int h = tid % HH, j = tid / HH;
        float m = -INFINITY;
        for (int i = j; i < dn; i += 8) m = fmaxf(m, lb[i * HH + h]);
        s_red[tid] = m;
    }
    __syncthreads();
    if (tid < HH) {
        float m = -INFINITY;
        #pragma unroll
        for (int j = 0; j < 8; j++) m = fmaxf(m, s_red[j * HH + tid]);
        if (!isfinite(m)) m = 0.f;
        s_amax[tid] = m;
    }
    __syncthreads();
    if (tid < 96) {
        int h = tid % HH, j = tid / HH;
        float am = s_amax[h];
        float s = 0.f;
        for (int i = j; i < dn; i += 8) s += __expf(lb[i * HH + h] - am);
        s_red[tid] = s;
    }
    __syncthreads();
    if (tid < HH) {
        float s = 0.f;
        #pragma unroll
        for (int j = 0; j < 8; j++) s += s_red[j * HH + tid];
        s_inv[tid] = 1.f / (s + 1e-16f);
    }
    __syncthreads();

    for (int idx = tid; idx < dn * HH; idx += 256) {
        int h = idx % HH;
        lb[idx] = __expf(lb[idx] - s_amax[h]) * s_inv[h];
    }
    __syncthreads();

    if (tid < 144) {
        int chunk = tid / 72;
        int c = tid % 72;
        int h = c / 6;
        float4 acc = {0.f, 0.f, 0.f, 0.f};
        #pragma unroll 8
        for (int i = chunk; i < dn; i += 2) {
            int dst = dl[i];
            float w = lb[i * HH + h];
            float4 v = h4_to_f4(*reinterpret_cast<const uint2*>(g_vpts16 + (size_t)dst * 288 + c * 4));
            acc.x += w * v.x; acc.y += w * v.y; acc.z += w * v.z; acc.w += w * v.w;
        }
        float* dstp = (chunk == 0) ? (sacc + 192 + c * 4) : (s_pt2 + c * 4);
        dstp[0] = acc.x; dstp[1] = acc.y; dstp[2] = acc.z; dstp[3] = acc.w;
    } else if (tid >= 160 && tid < 208) {
        int c = tid - 160;
        int h = c >> 2, c4 = c & 3;
        float4 acc = {0.f, 0.f, 0.f, 0.f};
        #pragma unroll 8
        for (int i = 0; i < dn; i++) {
            int dst = dl[i];
            float w = lb[i * HH + h];
            float4 v = h4_to_f4(*reinterpret_cast<const uint2*>(g_v16 + (size_t)dst * 192 + h * 16 + c4 * 4));
            acc.x += w * v.x; acc.y += w * v.y; acc.z += w * v.z; acc.w += w * v.w;
        }
        sacc[c * 4 + 0] = acc.x; sacc[c * 4 + 1] = acc.y;
        sacc[c * 4 + 2] = acc.z; sacc[c * 4 + 3] = acc.w;
    } else if (tid >= 224 && tid < 248) {
        int c = tid - 224;
        int j = c & 7, hq = c >> 3;
        float4 acc[4];
        #pragma unroll
        for (int r = 0; r < 4; r++) acc[r] = make_float4(0.f, 0.f, 0.f, 0.f);
        #pragma unroll 8
        for (int i = 0; i < dn; i++) {
            float4 p = h4_to_f4(*reinterpret_cast<const uint2*>(g_pz16 + (size_t)(beg + i) * 32 + j * 4));
            #pragma unroll
            for (int r = 0; r < 4; r++) {
                float w = lb[i * HH + hq * 4 + r];
                acc[r].x += w * p.x; acc[r].y += w * p.y;
                acc[r].z += w * p.z; acc[r].w += w * p.w;
            }
        }
        #pragma unroll
        for (int r = 0; r < 4; r++) {
            int base = 480 + (hq * 4 + r) * 32 + j * 4;
            sacc[base + 0] = acc[r].x; sacc[base + 1] = acc[r].y;
            sacc[base + 2] = acc[r].z; sacc[base + 3] = acc[r].w;
        }
    }
    __syncthreads();
    for (int t = tid; t < 288; t += 256) sacc[192 + t] += s_pt2[t];
    __syncthreads();

    __half* f = g_feats16 + (size_t)n * FEAT_COLS;
    if (tid < 192) f[tid] = __float2half(sacc[tid]);
    for (int t = tid; t < 384; t += 256) f[576 + t] = __float2half(sacc[480 + t]);
    if (tid < 96) {
        int q = tid;
        float g0 = sacc[192 + q * 3 + 0] - trans[(size_t)n * 3 + 0];
        float g1 = sacc[192 + q * 3 + 1] - trans[(size_t)n * 3 + 1];
        float g2 = sacc[192 + q * 3 + 2] - trans[(size_t)n * 3 + 2];
        const float* R = rot + (size_t)n * 9;
        float l0 = R[0] * g0 + R[3] * g1 + R[6] * g2;
        float l1 = R[1] * g0 + R[4] * g1 + R[7] * g2;
        float l2 = R[2] * g0 + R[5] * g1 + R[8] * g2;
        f[192 + q] = __float2half(l0);
        f[288 + q] = __float2half(l1);
        f[384 + q] = __float2half(l2);
        f[480 + q] = __float2half(sqrtf(l0 * l0 + l1 * l1 + l2 * l2 + 1e-8f));
    }
}

__global__ __launch_bounds__(256) void k_node(const float* __restrict__ mask,
                                              const float* __restrict__ head_weights,
                                              const float* __restrict__ rot,
                                              const float* __restrict__ trans) {
    __shared__ float4 s_q[48];
    __shared__ float4 s_qp[36];
    __shared__ float  s_hw[12];
    __shared__ float  s_logit[DN_FAST * HH];
    __shared__ int    s_dst[DN_FAST];
    __shared__ float  s_red[96];
    __shared__ float  s_amax[HH], s_inv[HH];
    __shared__ float  sacc[864];
    __shared__ float  s_pt2[288];

    int n = blockIdx.x;
    int tid = threadIdx.x;
    int beg = g_off[n], dn = g_off[n + 1] - beg;

    if (dn <= DN_FAST)
        node_body<true>(n, tid, beg, dn, mask, head_weights, rot, trans,
                        s_q, s_qp, s_hw, s_logit, s_dst, s_red, s_amax, s_inv, sacc, s_pt2);
    else
        node_body<false>(n, tid, beg, dn, mask, head_weights, rot, trans,
                         s_q, s_qp, s_hw, s_logit, s_dst, s_red, s_amax, s_inv, sacc, s_pt2);
}

// ---------------- launch ----------------
extern "C" void kernel_launch(void* const* d_in, const int* in_sizes, int n_in,
                              void* d_out, int out_size) {
    const float* s          = (const float*)d_in[0];
    const float* z          = (const float*)d_in[1];
    const int*   edge_index = (const int*)  d_in[2];
    const float* rot        = (const float*)d_in[3];
    const float* trans      = (const float*)d_in[4];
    const float* mask       = (const float*)d_in[5];
    const float* q_w        = (const float*)d_in[6];
    const float* q_b        = (const float*)d_in[7];
    const float* kv_w       = (const float*)d_in[8];
    const float* kv_b       = (const float*)d_in[9];
    const float* qp_w       = (const float*)d_in[10];
    const float* qp_b       = (const float*)d_in[11];
    const float* kvp_w      = (const float*)d_in[12];
    const float* kvp_b      = (const float*)d_in[13];
    const float* b_w        = (const float*)d_in[14];
    const float* b_b        = (const float*)d_in[15];
    const float* dz_w       = (const float*)d_in[16];
    const float* dz_b       = (const float*)d_in[17];
    const float* head_w     = (const float*)d_in[18];
    const float* out_w      = (const float*)d_in[19];
    const float* out_b      = (const float*)d_in[20];
    float* out = (float*)d_out;

    static cudaStream_t s2;
    static cudaEvent_t ev0, ev2;
    static int inited = 0;
    static bool streamsOK = false;
    if (!inited) {
        inited = 1;
        streamsOK =
            cudaStreamCreateWithFlags(&s2, cudaStreamNonBlocking) == cudaSuccess &&
            cudaEventCreateWithFlags(&ev0, cudaEventDisableTiming) == cudaSuccess &&
            cudaEventCreateWithFlags(&ev2, cudaEventDisableTiming) == cudaSuccess;
    }

    if (streamsOK) {
        cudaEventRecord(ev0, 0);
        cudaStreamWaitEvent(s2, ev0, 0);
        k_zero_hist<<<NN / 256, 256, 0, s2>>>();
        k_hist<<<NE / 256, 256, 0, s2>>>(edge_index);
        k_scan<<<1, 1024, 0, s2>>>();
        k_scatter<<<NE / 256, 256, 0, s2>>>(edge_index);
        k_pack_rest<<<(PACKR_TOTAL + 255) / 256, 256, 0, s2>>>(b_w, b_b, dz_w, dz_b, out_w);
        k_gemm_edge<<<NE / 128, 256, 0, s2>>>(z);
        cudaEventRecord(ev2, s2);

        k_pack_proj<<<(PACKP_TOTAL + 255) / 256, 256>>>(q_w, q_b, kv_w, kv_b,
                                                        qp_w, qp_b, kvp_w, kvp_b);
        k_gemm_proj<<<(PROJ_COLS / 128) * (NN / 128), 256>>>(s);
        k_pointify<<<(NN * 192) / 256, 256>>>(rot, trans);

        cudaStreamWaitEvent(0, ev2, 0);
        k_node<<<NN, 256>>>(mask, head_w, rot, trans);
        k_gemm_out<<<dim3(CS / 128, NN / 64), 256>>>(out_b, out);
    } else {
        k_pack_proj<<<(PACKP_TOTAL + 255) / 256, 256>>>(q_w, q_b, kv_w, kv_b,
                                                        qp_w, qp_b, kvp_w, kvp_b);
        k_pack_rest<<<(PACKR_TOTAL + 255) / 256, 256>>>(b_w, b_b, dz_w, dz_b, out_w);
        k_zero_hist<<<NN / 256, 256>>>();
        k_hist<<<NE / 256, 256>>>(edge_index);
        k_scan<<<1, 1024>>>();
        k_scatter<<<NE / 256, 256>>>(edge_index);
        k_gemm_edge<<<NE / 128, 256>>>(z);
        k_gemm_proj<<<(PROJ_COLS / 128) * (NN / 128), 256>>>(s);
        k_pointify<<<(NN * 192) / 256, 256>>>(rot, trans);
        k_node<<<NN, 256>>>(mask, head_w, rot, trans);
        k_gemm_out<<<dim3(CS / 128, NN / 64), 256>>>(out_b, out);
    }
}

// round 13
// speedup vs baseline: 1.0307x; 1.0307x over previous
#include <cuda_runtime.h>
#include <cuda_fp16.h>
#include <math.h>

#define NN 8192
#define NE 262144
#define CS 384
#define CZ 128
#define CH 16
#define HH 12
#define PQK 4
#define PV 8
#define PROJ_COLS 1152      // 192 q | 384 kv | 144 qp | 432 kvp
#define EDGE_COLS 44        // 12 b | 32 pz
#define FEAT_COLS 960
#define S_QK 0.14433756729740643f
#define S_B  0.5773502691896258f
#define S_PT 0.1360827634879543f
#define INF_C 100000.0f
#define DN_FAST 128

// ---------------- scratch ----------------
__device__ float  g_proj[(size_t)NN * PROJ_COLS];
__device__ float  g_qpts[(size_t)NN * 144];
__device__ float  g_kpts[(size_t)NN * 144];
__device__ __half g_k16[(size_t)NN * 192];
__device__ __half g_v16[(size_t)NN * 192];
__device__ __half g_vpts16[(size_t)NN * 288];
__device__ __half g_pz16[(size_t)NE * 32];
__device__ float  g_bE[(size_t)NE * 12];
__device__ float  g_abuf[(size_t)NE * HH];
__device__ __align__(16) __half g_feats16[(size_t)NN * FEAT_COLS];
__device__ int    g_rank[NE];
__device__ int    g_dstOf[NE];
__device__ int    g_hist[NN];
__device__ int    g_off[NN + 1];
__device__ int    g_cursor[NN];
__device__ unsigned g_Wp16[(CS / 2) * PROJ_COLS];
__device__ unsigned g_We16[(CZ / 2) * EDGE_COLS];
__device__ unsigned g_Wo16[(FEAT_COLS / 2) * CS];
__device__ float    g_Bproj[PROJ_COLS];
__device__ float    g_Bedge[EDGE_COLS];

__device__ __forceinline__ unsigned pack_h2(float x, float y) {
    __half2 h = __floats2half2_rn(x, y);
    return *reinterpret_cast<unsigned*>(&h);
}

// ---------------- weight packing ----------------
#define SEG0 ((CS / 2) * PROJ_COLS)
#define SEG1 ((CZ / 2) * EDGE_COLS)
#define SEG2 ((FEAT_COLS / 2) * CS)
#define PACKP_TOTAL (SEG0 + PROJ_COLS)
#define PACKR_TOTAL (SEG1 + SEG2 + EDGE_COLS)

__device__ __forceinline__ float projw(int k, int col,
                                       const float* q_w, const float* kv_w,
                                       const float* qp_w, const float* kvp_w) {
    if (col < 192)  return q_w[k * 192 + col];
    if (col < 576)  return kv_w[k * 384 + (col - 192)];
    if (col < 720)  return qp_w[k * 144 + (col - 576)];
    return kvp_w[k * 432 + (col - 720)];
}

__global__ void k_pack_proj(const float* __restrict__ q_w, const float* __restrict__ q_b,
                            const float* __restrict__ kv_w, const float* __restrict__ kv_b,
                            const float* __restrict__ qp_w, const float* __restrict__ qp_b,
                            const float* __restrict__ kvp_w, const float* __restrict__ kvp_b) {
    int gid = blockIdx.x * blockDim.x + threadIdx.x;
    if (gid < SEG0) {
        int r2 = gid / PROJ_COLS, col = gid % PROJ_COLS;
        g_Wp16[gid] = pack_h2(projw(2 * r2, col, q_w, kv_w, qp_w, kvp_w),
                              projw(2 * r2 + 1, col, q_w, kv_w, qp_w, kvp_w));
    } else if (gid < PACKP_TOTAL) {
        int j = gid - SEG0;
        float v;
        if (j < 192)      v = q_b[j];
        else if (j < 576) v = kv_b[j - 192];
        else if (j < 720) v = qp_b[j - 576];
        else              v = kvp_b[j - 720];
        g_Bproj[j] = v;
    }
}

__global__ void k_pack_rest(const float* __restrict__ b_w, const float* __restrict__ b_b,
                            const float* __restrict__ dz_w, const float* __restrict__ dz_b,
                            const float* __restrict__ out_w) {
    int gid = blockIdx.x * blockDim.x + threadIdx.x;
    if (gid < SEG1) {
        int r2 = gid / EDGE_COLS, c = gid % EDGE_COLS;
        float v0 = (c < 12) ? b_w[(2 * r2) * 12 + c] : dz_w[(2 * r2) * 32 + (c - 12)];
        float v1 = (c < 12) ? b_w[(2 * r2 + 1) * 12 + c] : dz_w[(2 * r2 + 1) * 32 + (c - 12)];
        g_We16[gid] = pack_h2(v0, v1);
    } else if (gid < SEG1 + SEG2) {
        int j = gid - SEG1;
        int r2 = j / CS, c = j % CS;
        g_Wo16[j] = pack_h2(out_w[(size_t)(2 * r2) * CS + c],
                            out_w[(size_t)(2 * r2 + 1) * CS + c]);
    } else if (gid < PACKR_TOTAL) {
        int c = gid - SEG1 - SEG2;
        g_Bedge[c] = (c < 12) ? b_b[c] : dz_b[c - 12];
    }
}

// ---------------- sorting ----------------
__global__ void k_zero_hist() {
    int i = blockIdx.x * blockDim.x + threadIdx.x;
    if (i < NN) g_hist[i] = 0;
}
__global__ void k_hist(const int* __restrict__ edge_index) {
    int e = blockIdx.x * blockDim.x + threadIdx.x;
    if (e < NE) atomicAdd(&g_hist[edge_index[NE + e]], 1);
}
__global__ void k_scan() {
    __shared__ int wsum[32];
    int tid = threadIdx.x;
    int lane = tid & 31, wid = tid >> 5;
    int base = tid * 8;
    int local[8];
    int s = 0;
    #pragma unroll
    for (int i = 0; i < 8; i++) { local[i] = g_hist[base + i]; s += local[i]; }
    int v = s;
    #pragma unroll
    for (int d = 1; d < 32; d <<= 1) {
        int t = __shfl_up_sync(0xffffffffu, v, d);
        if (lane >= d) v += t;
    }
    if (lane == 31) wsum[wid] = v;
    __syncthreads();
    if (wid == 0) {
        int w = wsum[lane];
        #pragma unroll
        for (int d = 1; d < 32; d <<= 1) {
            int t = __shfl_up_sync(0xffffffffu, w, d);
            if (lane >= d) w += t;
        }
        wsum[lane] = w;
    }
    __syncthreads();
    int run = v - s + (wid > 0 ? wsum[wid - 1] : 0);
    #pragma unroll
    for (int i = 0; i < 8; i++) {
        g_off[base + i] = run;
        g_cursor[base + i] = run;
        run += local[i];
    }
    if (tid == 1023) g_off[NN] = run;
}
__global__ void k_scatter(const int* __restrict__ edge_index) {
    int e = blockIdx.x * blockDim.x + threadIdx.x;
    if (e >= NE) return;
    int src = edge_index[NE + e];
    int dst = edge_index[e];
    int pos = atomicAdd(&g_cursor[src], 1);
    g_rank[e] = pos;
    g_dstOf[pos] = dst;
}

// ---------------- fp16 mma helper ----------------
__device__ __forceinline__ void mma_f16(float* c, unsigned a0, unsigned a1, unsigned a2,
                                        unsigned a3, unsigned b0, unsigned b1) {
    asm volatile("mma.sync.aligned.m16n8k16.row.col.f32.f16.f16.f32 "
                 "{%0,%1,%2,%3}, {%4,%5,%6,%7}, {%8,%9}, {%0,%1,%2,%3};"
                 : "+f"(c[0]), "+f"(c[1]), "+f"(c[2]), "+f"(c[3])
                 : "r"(a0), "r"(a1), "r"(a2), "r"(a3), "r"(b0), "r"(b1));
}

#define AP2 136
#define BP2 136
#define EBP2 72
#define SMEM_ARENA 17408

__device__ __forceinline__ void proj_store2(int r, int col, float v0, float v1) {
    if (col >= 192 && col < 576) {
        int u = col - 192;
        int h = u >> 5, c = u & 31;
        __half2 hv = __floats2half2_rn(v0, v1);
        if (c < 16) *reinterpret_cast<__half2*>(&g_k16[(size_t)r * 192 + h * 16 + c]) = hv;
        else        *reinterpret_cast<__half2*>(&g_v16[(size_t)r * 192 + h * 16 + (c - 16)]) = hv;
    } else {
        float2 fv = make_float2(v0, v1);
        *reinterpret_cast<float2*>(&g_proj[(size_t)r * PROJ_COLS + col]) = fv;
    }
}

// ---------------- pipelined 128x128 fp16 GEMM ----------------
template <int N, int K, int MODE>
__device__ __forceinline__ void gemm128_f16(const void* __restrict__ Aptr,
                                            const unsigned* __restrict__ W16,
                                            const float* __restrict__ Bias,
                                            float* __restrict__ C,
                                            int row0, int col0, char* smemraw) {
    unsigned (*As)[8][AP2] = reinterpret_cast<unsigned (*)[8][AP2]>(smemraw);
    unsigned (*Bs)[8][BP2] = reinterpret_cast<unsigned (*)[8][BP2]>(smemraw + 2 * 8 * AP2 * 4);
    const float*  Af = (const float*)Aptr;
    const __half* Ah = (const __half*)Aptr;
    const int tid = threadIdx.x;
    const int lane = tid & 31, w = tid >> 5;
    const int gid = lane >> 2, tig = lane & 3;
    const int wm = (w & 1) * 64;
    const int wn = (w >> 1) * 32;

    float acc[4][4][4];
    #pragma unroll
    for (int mt = 0; mt < 4; mt++)
        #pragma unroll
        for (int nt = 0; nt < 4; nt++)
            #pragma unroll
            for (int i = 0; i < 4; i++) acc[mt][nt][i] = 0.f;

    float4 pa[2];
    uint4  pah;
    unsigned pb[4];

    if (MODE == 2) {
        int m = tid >> 1, k8 = (tid & 1) * 8;
        pah = *reinterpret_cast<const uint4*>(&Ah[(size_t)(row0 + m) * K + k8]);
    } else {
        #pragma unroll
        for (int l = 0; l < 2; l++) {
            int idx = tid + 256 * l;
            int m = idx >> 2, kq = (idx & 3) * 4;
            pa[l] = *reinterpret_cast<const float4*>(&Af[(size_t)(row0 + m) * K + kq]);
        }
    }
    #pragma unroll
    for (int l = 0; l < 4; l++) {
        int idx = tid + 256 * l;
        int r = idx >> 7, c = idx & 127;
        pb[l] = W16[(size_t)r * N + col0 + c];
    }
    if (MODE == 2) {
        int m = tid >> 1, k2 = (tid & 1) * 4;
        As[0][k2 + 0][m] = pah.x;
        As[0][k2 + 1][m] = pah.y;
        As[0][k2 + 2][m] = pah.z;
        As[0][k2 + 3][m] = pah.w;
    } else {
        #pragma unroll
        for (int l = 0; l < 2; l++) {
            int idx = tid + 256 * l;
            int m = idx >> 2, k2 = (idx & 3) * 2;
            As[0][k2 + 0][m] = pack_h2(pa[l].x, pa[l].y);
            As[0][k2 + 1][m] = pack_h2(pa[l].z, pa[l].w);
        }
    }
    #pragma unroll
    for (int l = 0; l < 4; l++) {
        int idx = tid + 256 * l;
        Bs[0][idx >> 7][idx & 127] = pb[l];
    }
    __syncthreads();

    const int nIter = K / 16;
    for (int it = 0; it < nIter; it++) {
        int buf = it & 1;
        if (it + 1 < nIter) {
            int k0 = (it + 1) * 16;
            if (MODE == 2) {
                int m = tid >> 1, k8 = (tid & 1) * 8;
                pah = *reinterpret_cast<const uint4*>(&Ah[(size_t)(row0 + m) * K + k0 + k8]);
            } else {
                #pragma unroll
                for (int l = 0; l < 2; l++) {
                    int idx = tid + 256 * l;
                    int m = idx >> 2, kq = (idx & 3) * 4;
                    pa[l] = *reinterpret_cast<const float4*>(&Af[(size_t)(row0 + m) * K + k0 + kq]);
                }
            }
            #pragma unroll
            for (int l = 0; l < 4; l++) {
                int idx = tid + 256 * l;
                int r = idx >> 7, c = idx & 127;
                pb[l] = W16[(size_t)(k0 / 2 + r) * N + col0 + c];
            }
        }
        {
            unsigned a[4][4], b[4][2];
            #pragma unroll
            for (int mt = 0; mt < 4; mt++) {
                int m0 = wm + mt * 16;
                a[mt][0] = As[buf][tig][m0 + gid];
                a[mt][1] = As[buf][tig][m0 + gid + 8];
                a[mt][2] = As[buf][tig + 4][m0 + gid];
                a[mt][3] = As[buf][tig + 4][m0 + gid + 8];
            }
            #pragma unroll
            for (int nt = 0; nt < 4; nt++) {
                int n0 = wn + nt * 8;
                b[nt][0] = Bs[buf][tig][n0 + gid];
                b[nt][1] = Bs[buf][tig + 4][n0 + gid];
            }
            #pragma unroll
            for (int mt = 0; mt < 4; mt++)
                #pragma unroll
                for (int nt = 0; nt < 4; nt++)
                    mma_f16(acc[mt][nt], a[mt][0], a[mt][1], a[mt][2], a[mt][3],
                            b[nt][0], b[nt][1]);
        }
        if (it + 1 < nIter) {
            int nb = 1 - buf;
            if (MODE == 2) {
                int m = tid >> 1, k2 = (tid & 1) * 4;
                As[nb][k2 + 0][m] = pah.x;
                As[nb][k2 + 1][m] = pah.y;
                As[nb][k2 + 2][m] = pah.z;
                As[nb][k2 + 3][m] = pah.w;
            } else {
                #pragma unroll
                for (int l = 0; l < 2; l++) {
                    int idx = tid + 256 * l;
                    int m = idx >> 2, k2 = (idx & 3) * 2;
                    As[nb][k2 + 0][m] = pack_h2(pa[l].x, pa[l].y);
                    As[nb][k2 + 1][m] = pack_h2(pa[l].z, pa[l].w);
                }
            }
            #pragma unroll
            for (int l = 0; l < 4; l++) {
                int idx = tid + 256 * l;
                Bs[nb][idx >> 7][idx & 127] = pb[l];
            }
        }
        __syncthreads();
    }
    #pragma unroll
    for (int mt = 0; mt < 4; mt++) {
        #pragma unroll
        for (int i = 0; i < 2; i++) {
            int r = row0 + wm + mt * 16 + gid + i * 8;
            #pragma unroll
            for (int nt = 0; nt < 4; nt++) {
                int cb = col0 + wn + nt * 8 + 2 * tig;
                float v0 = acc[mt][nt][i * 2 + 0] + Bias[cb + 0];
                float v1 = acc[mt][nt][i * 2 + 1] + Bias[cb + 1];
                if (MODE == 1) proj_store2(r, cb, v0, v1);
                else {
                    C[(size_t)r * N + cb]     = v0;
                    C[(size_t)r * N + cb + 1] = v1;
                }
            }
        }
    }
}

// ---------------- pipelined 128x64 fp16 edge GEMM ----------------
__device__ __forceinline__ void edge_gemm_f16(const float* __restrict__ A,
                                              const unsigned* __restrict__ W16,
                                              const float* __restrict__ Bias,
                                              const int* __restrict__ rowmap,
                                              int row0, char* smemraw) {
    unsigned (*As)[8][AP2] = reinterpret_cast<unsigned (*)[8][AP2]>(smemraw);
    unsigned (*Bs)[8][EBP2] = reinterpret_cast<unsigned (*)[8][EBP2]>(smemraw + 2 * 8 * AP2 * 4);
    const int tid = threadIdx.x;
    const int lane = tid & 31, w = tid >> 5;
    const int gid = lane >> 2, tig = lane & 3;
    const int wm = (w & 3) * 32;
    const int wn = (w >> 2) * 32;
    const int N = EDGE_COLS, K = CZ;

    float c[2][4][4];
    #pragma unroll
    for (int mt = 0; mt < 2; mt++)
        #pragma unroll
        for (int nt = 0; nt < 4; nt++)
            #pragma unroll
            for (int i = 0; i < 4; i++) c[mt][nt][i] = 0.f;

    float4 pa[2];
    unsigned pb[2];

    #pragma unroll
    for (int l = 0; l < 2; l++) {
        int idx = tid + 256 * l;
        int r = idx >> 2, kc = (idx & 3) * 4;
        pa[l] = *reinterpret_cast<const float4*>(&A[(size_t)(row0 + r) * K + kc]);
    }
    #pragma unroll
    for (int l = 0; l < 2; l++) {
        int idx = tid + 256 * l;
        int r = idx >> 6, cc = idx & 63;
        pb[l] = (cc < N) ? W16[(size_t)r * N + cc] : 0u;
    }
    #pragma unroll
    for (int l = 0; l < 2; l++) {
        int idx = tid + 256 * l;
        int r = idx >> 2, k2 = (idx & 3) * 2;
        As[0][k2 + 0][r] = pack_h2(pa[l].x, pa[l].y);
        As[0][k2 + 1][r] = pack_h2(pa[l].z, pa[l].w);
    }
    #pragma unroll
    for (int l = 0; l < 2; l++) {
        int idx = tid + 256 * l;
        Bs[0][idx >> 6][idx & 63] = pb[l];
    }
    __syncthreads();

    const int nIter = K / 16;
    for (int it = 0; it < nIter; it++) {
        int buf = it & 1;
        if (it + 1 < nIter) {
            int k0 = (it + 1) * 16;
            #pragma unroll
            for (int l = 0; l < 2; l++) {
                int idx = tid + 256 * l;
                int r = idx >> 2, kc = (idx & 3) * 4;
                pa[l] = *reinterpret_cast<const float4*>(&A[(size_t)(row0 + r) * K + k0 + kc]);
            }
            #pragma unroll
            for (int l = 0; l < 2; l++) {
                int idx = tid + 256 * l;
                int r = idx >> 6, cc = idx & 63;
                pb[l] = (cc < N) ? W16[(size_t)(k0 / 2 + r) * N + cc] : 0u;
            }
        }
        {
            unsigned a[2][4], b[4][2];
            #pragma unroll
            for (int mt = 0; mt < 2; mt++) {
                int m0 = wm + mt * 16;
                a[mt][0] = As[buf][tig][m0 + gid];
                a[mt][1] = As[buf][tig][m0 + gid + 8];
                a[mt][2] = As[buf][tig + 4][m0 + gid];
                a[mt][3] = As[buf][tig + 4][m0 + gid + 8];
            }
            #pragma unroll
            for (int nt = 0; nt < 4; nt++) {
                int n0 = wn + nt * 8;
                b[nt][0] = Bs[buf][tig][n0 + gid];
                b[nt][1] = Bs[buf][tig + 4][n0 + gid];
            }
            #pragma unroll
            for (int mt = 0; mt < 2; mt++)
                #pragma unroll
                for (int nt = 0; nt < 4; nt++)
                    mma_f16(c[mt][nt], a[mt][0], a[mt][1], a[mt][2], a[mt][3],
                            b[nt][0], b[nt][1]);
        }
        if (it + 1 < nIter) {
            int nb = 1 - buf;
            #pragma unroll
            for (int l = 0; l < 2; l++) {
                int idx = tid + 256 * l;
                int r = idx >> 2, k2 = (idx & 3) * 2;
                As[nb][k2 + 0][r] = pack_h2(pa[l].x, pa[l].y);
                As[nb][k2 + 1][r] = pack_h2(pa[l].z, pa[l].w);
            }
            #pragma unroll
            for (int l = 0; l < 2; l++) {
                int idx = tid + 256 * l;
                Bs[nb][idx >> 6][idx & 63] = pb[l];
            }
        }
        __syncthreads();
    }
    #pragma unroll
    for (int mt = 0; mt < 2; mt++) {
        #pragma unroll
        for (int i = 0; i < 2; i++) {
            int r = row0 + wm + mt * 16 + gid + i * 8;
            int crow = rowmap[r];
            #pragma unroll
            for (int nt = 0; nt < 4; nt++) {
                int cbase = wn + nt * 8 + 2 * tig;
                #pragma unroll
                for (int j = 0; j < 2; j++) {
                    int cc = cbase + j;
                    if (cc < N) {
                        float val = c[mt][nt][i * 2 + j] + Bias[cc];
                        if (cc < 12) g_bE[(size_t)crow * 12 + cc] = val;
                        else         g_pz16[(size_t)crow * 32 + (cc - 12)] = __float2half(val);
                    }
                }
            }
        }
    }
}

__global__ __launch_bounds__(256, 2) void k_gemm_proj(const float* __restrict__ s) {
    __shared__ __align__(16) char smemraw[SMEM_ARENA];
    int b = blockIdx.x;
    gemm128_f16<PROJ_COLS, CS, 1>(s, g_Wp16, g_Bproj, nullptr,
                                  (b / 9) * 128, (b % 9) * 128, smemraw);
}
__global__ __launch_bounds__(256, 2) void k_gemm_edge(const float* __restrict__ z) {
    __shared__ __align__(16) char smemraw[SMEM_ARENA];
    edge_gemm_f16(z, g_We16, g_Bedge, g_rank, blockIdx.x * 128, smemraw);
}
__global__ __launch_bounds__(256, 2) void k_gemm_out(const float* __restrict__ out_b,
                                                     float* __restrict__ out) {
    __shared__ __align__(16) char smemraw[SMEM_ARENA];
    gemm128_f16<CS, FEAT_COLS, 2>(g_feats16, g_Wo16, out_b, out,
                                  blockIdx.y * 128, blockIdx.x * 128, smemraw);
}

// ---------------- point transform ----------------
__global__ void k_pointify(const float* __restrict__ rot, const float* __restrict__ trans) {
    int gid = blockIdx.x * blockDim.x + threadIdx.x;
    if (gid >= NN * 192) return;
    int n = gid / 192;
    int p_all = gid % 192;
    const float* R = rot + (size_t)n * 9;
    const float* T = trans + (size_t)n * 3;
    const float* pr = g_proj + (size_t)n * PROJ_COLS;
    if (p_all < 48) {
        int p = p_all;
        float y0 = pr[576 + 0 * 48 + p];
        float y1 = pr[576 + 1 * 48 + p];
        float y2 = pr[576 + 2 * 48 + p];
        #pragma unroll
        for (int i = 0; i < 3; i++) {
            float v = R[i * 3 + 0] * y0 + R[i * 3 + 1] * y1 + R[i * 3 + 2] * y2 + T[i];
            g_qpts[((size_t)n * 48 + p) * 3 + i] = v;
        }
    } else {
        int p = p_all - 48;
        float y0 = pr[720 + 0 * 144 + p];
        float y1 = pr[720 + 1 * 144 + p];
        float y2 = pr[720 + 2 * 144 + p];
        int h = p / 12, j = p % 12;
        #pragma unroll
        for (int i = 0; i < 3; i++) {
            float v = R[i * 3 + 0] * y0 + R[i * 3 + 1] * y1 + R[i * 3 + 2] * y2 + T[i];
            if (j < PQK) g_kpts[((size_t)n * 48 + h * 4 + j) * 3 + i] = v;
            else         g_vpts16[(size_t)n * 288 + (h * 8 + (j - 4)) * 3 + i] = __float2half(v);
        }
    }
}

// ---------------- fused per-node: logits + softmax + aggregation ----------------
__device__ __forceinline__ float4 h4_to_f4(uint2 u) {
    __half2* hp = reinterpret_cast<__half2*>(&u);
    float2 f0 = __half22float2(hp[0]);
    float2 f1 = __half22float2(hp[1]);
    return make_float4(f0.x, f0.y, f1.x, f1.y);
}

template <bool FAST>
__device__ __forceinline__ void node_body(
    int n, int tid, int beg, int dn,
    const float* __restrict__ mask, const float* __restrict__ head_weights,
    const float* __restrict__ rot, const float* __restrict__ trans,
    float4* s_q, float4* s_qp, float* s_hw, float* s_logit, int* s_dst,
    float* s_red, float* s_amax, float* s_inv, float* sacc, float* s_pt2) {

    const float4* proj4 = reinterpret_cast<const float4*>(g_proj);
    const float4* kpts4 = reinterpret_cast<const float4*>(g_kpts);

    float* lb = FAST ? s_logit : (g_abuf + (size_t)beg * HH);
    const int* dl = FAST ? s_dst : (g_dstOf + beg);

    if (tid < 48) s_q[tid] = proj4[(size_t)n * 288 + tid];
    else if (tid < 84) s_qp[tid - 48] = reinterpret_cast<const float4*>(g_qpts)[(size_t)n * 36 + (tid - 48)];
    else if (tid < 96) s_hw[tid - 84] = 0.5f * S_PT * log1pf(expf(head_weights[tid - 84]));
    if (FAST) {
        for (int i = tid; i < dn; i += 256) s_dst[i] = g_dstOf[beg + i];
    }
    __syncthreads();

    float mn = mask[n];

    if (tid < 252) {
        int h = tid % HH;
        float4 q0 = s_q[h * 4 + 0], q1 = s_q[h * 4 + 1], q2 = s_q[h * 4 + 2], q3 = s_q[h * 4 + 3];
        float4 p0 = s_qp[h * 3 + 0], p1 = s_qp[h * 3 + 1], p2 = s_qp[h * 3 + 2];
        float hwv = s_hw[h];
        for (int i = tid / HH; i < dn; i += 21) {
            int dst = dl[i];
            const uint4* kh = reinterpret_cast<const uint4*>(g_k16 + (size_t)dst * 192 + h * 16);
            uint4 u0 = kh[0], u1 = kh[1];
            __half2* h0 = reinterpret_cast<__half2*>(&u0);
            __half2* h1 = reinterpret_cast<__half2*>(&u1);
            float2 f0 = __half22float2(h0[0]), f1 = __half22float2(h0[1]);
            float2 f2 = __half22float2(h0[2]), f3 = __half22float2(h0[3]);
            float2 f4 = __half22float2(h1[0]), f5 = __half22float2(h1[1]);
            float2 f6 = __half22float2(h1[2]), f7 = __half22float2(h1[3]);
            float dot = q0.x * f0.x + q0.y * f0.y + q0.z * f1.x + q0.w * f1.y
                      + q1.x * f2.x + q1.y * f2.y + q1.z * f3.x + q1.w * f3.y
                      + q2.x * f4.x + q2.y * f4.y + q2.z * f5.x + q2.w * f5.y
                      + q3.x * f6.x + q3.y * f6.y + q3.z * f7.x + q3.w * f7.y;
            const float4* kp = kpts4 + (size_t)dst * 36 + h * 3;
            float4 d0 = kp[0], d1 = kp[1], d2 = kp[2];
            float pt = 0.f;
            pt += (p0.x - d0.x) * (p0.x - d0.x) + (p0.y - d0.y) * (p0.y - d0.y)
                + (p0.z - d0.z) * (p0.z - d0.z) + (p0.w - d0.w) * (p0.w - d0.w);
            pt += (p1.x - d1.x) * (p1.x - d1.x) + (p1.y - d1.y) * (p1.y - d1.y)
                + (p1.z - d1.z) * (p1.z - d1.z) + (p1.w - d1.w) * (p1.w - d1.w);
            pt += (p2.x - d2.x) * (p2.x - d2.x) + (p2.y - d2.y) * (p2.y - d2.y)
                + (p2.z - d2.z) * (p2.z - d2.z) + (p2.w - d2.w) * (p2.w - d2.w);
            float b = g_bE[(size_t)(beg + i) * 12 + h];
            float em = INF_C * (mask[dst] * mn - 1.f);
            lb[i * HH + h] = dot * S_QK + S_B * b - hwv * pt + em;
        }
    }
    __syncthreads();

    if (tid < 96) {
        int h = tid % HH, j = tid / HH;
        float m = -INFINITY;
        for (int i = j; i < dn; i += 8) m = fmaxf(m, lb[i * HH + h]);
        s_red[tid] = m;
    }
    __syncthreads();
    if (tid < HH) {
        float m = -INFINITY;
        #pragma unroll
        for (int j = 0; j < 8; j++) m = fmaxf(m, s_red[j * HH + tid]);
        if (!isfinite(m)) m = 0.f;
        s_amax[tid] = m;
    }
    __syncthreads();
    if (tid < 96) {
        int h = tid % HH, j = tid / HH;
        float am = s_amax[h];
        float s = 0.f;
        for (int i = j; i < dn; i += 8) s += __expf(lb[i * HH + h] - am);
        s_red[tid] = s;
    }
    __syncthreads();
    if (tid < HH) {
        float s = 0.f;
        #pragma unroll
        for (int j = 0; j < 8; j++) s += s_red[j * HH + tid];
        s_inv[tid] = 1.f / (s + 1e-16f);
    }
    __syncthreads();

    for (int idx = tid; idx < dn * HH; idx += 256) {
        int h = idx % HH;
        lb[idx] = __expf(lb[idx] - s_amax[h]) * s_inv[h];
    }
    __syncthreads();

    if (tid < 144) {
        int chunk = tid / 72;
        int c = tid % 72;
        int h = c / 6;
        float4 acc = {0.f, 0.f, 0.f, 0.f};
        #pragma unroll 8
        for (int i = chunk; i < dn; i += 2) {
            int dst = dl[i];
            float w = lb[i * HH + h];
            float4 v = h4_to_f4(*reinterpret_cast<const uint2*>(g_vpts16 + (size_t)dst * 288 + c * 4));
            acc.x += w * v.x; acc.y += w * v.y; acc.z += w * v.z; acc.w += w * v.w;
        }
        float* dstp = (chunk == 0) ? (sacc + 192 + c * 4) : (s_pt2 + c * 4);
        dstp[0] = acc.x; dstp[1] = acc.y; dstp[2] = acc.z; dstp[3] = acc.w;
    } else if (tid >= 160 && tid < 208) {
        int c = tid - 160;
        int h = c >> 2, c4 = c & 3;
        float4 acc = {0.f, 0.f, 0.f, 0.f};
        #pragma unroll 8
        for (int i = 0; i < dn; i++) {
            int dst = dl[i];
            float w = lb[i * HH + h];
            float4 v = h4_to_f4(*reinterpret_cast<const uint2*>(g_v16 + (size_t)dst * 192 + h * 16 + c4 * 4));
            acc.x += w * v.x; acc.y += w * v.y; acc.z += w * v.z; acc.w += w * v.w;
        }
        sacc[c * 4 + 0] = acc.x; sacc[c * 4 + 1] = acc.y;
        sacc[c * 4 + 2] = acc.z; sacc[c * 4 + 3] = acc.w;
    } else if (tid >= 224 && tid < 248) {
        int c = tid - 224;
        int j = c & 7, hq = c >> 3;
        float4 acc[4];
        #pragma unroll
        for (int r = 0; r < 4; r++) acc[r] = make_float4(0.f, 0.f, 0.f, 0.f);
        #pragma unroll 8
        for (int i = 0; i < dn; i++) {
            float4 p = h4_to_f4(*reinterpret_cast<const uint2*>(g_pz16 + (size_t)(beg + i) * 32 + j * 4));
            #pragma unroll
            for (int r = 0; r < 4; r++) {
                float w = lb[i * HH + hq * 4 + r];
                acc[r].x += w * p.x; acc[r].y += w * p.y;
                acc[r].z += w * p.z; acc[r].w += w * p.w;
            }
        }
        #pragma unroll
        for (int r = 0; r < 4; r++) {
            int base = 480 + (hq * 4 + r) * 32 + j * 4;
            sacc[base + 0] = acc[r].x; sacc[base + 1] = acc[r].y;
            sacc[base + 2] = acc[r].z; sacc[base + 3] = acc[r].w;
        }
    }
    __syncthreads();
    for (int t = tid; t < 288; t += 256) sacc[192 + t] += s_pt2[t];
    __syncthreads();

    __half* f = g_feats16 + (size_t)n * FEAT_COLS;
    if (tid < 192) f[tid] = __float2half(sacc[tid]);
    for (int t = tid; t < 384; t += 256) f[576 + t] = __float2half(sacc[480 + t]);
    if (tid < 96) {
        int q = tid;
        float g0 = sacc[192 + q * 3 + 0] - trans[(size_t)n * 3 + 0];
        float g1 = sacc[192 + q * 3 + 1] - trans[(size_t)n * 3 + 1];
        float g2 = sacc[192 + q * 3 + 2] - trans[(size_t)n * 3 + 2];
        const float* R = rot + (size_t)n * 9;
        float l0 = R[0] * g0 + R[3] * g1 + R[6] * g2;
        float l1 = R[1] * g0 + R[4] * g1 + R[7] * g2;
        float l2 = R[2] * g0 + R[5] * g1 + R[8] * g2;
        f[192 + q] = __float2half(l0);
        f[288 + q] = __float2half(l1);
        f[384 + q] = __float2half(l2);
        f[480 + q] = __float2half(sqrtf(l0 * l0 + l1 * l1 + l2 * l2 + 1e-8f));
    }
}

__global__ __launch_bounds__(256) void k_node(const float* __restrict__ mask,
                                              const float* __restrict__ head_weights,
                                              const float* __restrict__ rot,
                                              const float* __restrict__ trans) {
    __shared__ float4 s_q[48];
    __shared__ float4 s_qp[36];
    __shared__ float  s_hw[12];
    __shared__ float  s_logit[DN_FAST * HH];
    __shared__ int    s_dst[DN_FAST];
    __shared__ float  s_red[96];
    __shared__ float  s_amax[HH], s_inv[HH];
    __shared__ float  sacc[864];
    __shared__ float  s_pt2[288];

    int n = blockIdx.x;
    int tid = threadIdx.x;
    int beg = g_off[n], dn = g_off[n + 1] - beg;

    if (dn <= DN_FAST)
        node_body<true>(n, tid, beg, dn, mask, head_weights, rot, trans,
                        s_q, s_qp, s_hw, s_logit, s_dst, s_red, s_amax, s_inv, sacc, s_pt2);
    else
        node_body<false>(n, tid, beg, dn, mask, head_weights, rot, trans,
                         s_q, s_qp, s_hw, s_logit, s_dst, s_red, s_amax, s_inv, sacc, s_pt2);
}

// ---------------- launch ----------------
extern "C" void kernel_launch(void* const* d_in, const int* in_sizes, int n_in,
                              void* d_out, int out_size) {
    const float* s          = (const float*)d_in[0];
    const float* z          = (const float*)d_in[1];
    const int*   edge_index = (const int*)  d_in[2];
    const float* rot        = (const float*)d_in[3];
    const float* trans      = (const float*)d_in[4];
    const float* mask       = (const float*)d_in[5];
    const float* q_w        = (const float*)d_in[6];
    const float* q_b        = (const float*)d_in[7];
    const float* kv_w       = (const float*)d_in[8];
    const float* kv_b       = (const float*)d_in[9];
    const float* qp_w       = (const float*)d_in[10];
    const float* qp_b       = (const float*)d_in[11];
    const float* kvp_w      = (const float*)d_in[12];
    const float* kvp_b      = (const float*)d_in[13];
    const float* b_w        = (const float*)d_in[14];
    const float* b_b        = (const float*)d_in[15];
    const float* dz_w       = (const float*)d_in[16];
    const float* dz_b       = (const float*)d_in[17];
    const float* head_w     = (const float*)d_in[18];
    const float* out_w      = (const float*)d_in[19];
    const float* out_b      = (const float*)d_in[20];
    float* out = (float*)d_out;

    static cudaStream_t s2;
    static cudaEvent_t ev0, ev2;
    static int inited = 0;
    static bool streamsOK = false;
    if (!inited) {
        inited = 1;
        streamsOK =
            cudaStreamCreateWithFlags(&s2, cudaStreamNonBlocking) == cudaSuccess &&
            cudaEventCreateWithFlags(&ev0, cudaEventDisableTiming) == cudaSuccess &&
            cudaEventCreateWithFlags(&ev2, cudaEventDisableTiming) == cudaSuccess;
    }

    if (streamsOK) {
        cudaEventRecord(ev0, 0);
        cudaStreamWaitEvent(s2, ev0, 0);
        k_zero_hist<<<NN / 256, 256, 0, s2>>>();
        k_hist<<<NE / 256, 256, 0, s2>>>(edge_index);
        k_scan<<<1, 1024, 0, s2>>>();
        k_scatter<<<NE / 256, 256, 0, s2>>>(edge_index);
        k_pack_rest<<<(PACKR_TOTAL + 255) / 256, 256, 0, s2>>>(b_w, b_b, dz_w, dz_b, out_w);
        k_gemm_edge<<<NE / 128, 256, 0, s2>>>(z);
        cudaEventRecord(ev2, s2);

        k_pack_proj<<<(PACKP_TOTAL + 255) / 256, 256>>>(q_w, q_b, kv_w, kv_b,
                                                        qp_w, qp_b, kvp_w, kvp_b);
        k_gemm_proj<<<(PROJ_COLS / 128) * (NN / 128), 256>>>(s);
        k_pointify<<<(NN * 192) / 256, 256>>>(rot, trans);

        cudaStreamWaitEvent(0, ev2, 0);
        k_node<<<NN, 256>>>(mask, head_w, rot, trans);
        k_gemm_out<<<dim3(CS / 128, NN / 128), 256>>>(out_b, out);
    } else {
        k_pack_proj<<<(PACKP_TOTAL + 255) / 256, 256>>>(q_w, q_b, kv_w, kv_b,
                                                        qp_w, qp_b, kvp_w, kvp_b);
        k_pack_rest<<<(PACKR_TOTAL + 255) / 256, 256>>>(b_w, b_b, dz_w, dz_b, out_w);
        k_zero_hist<<<NN / 256, 256>>>();
        k_hist<<<NE / 256, 256>>>(edge_index);
        k_scan<<<1, 1024>>>();
        k_scatter<<<NE / 256, 256>>>(edge_index);
        k_gemm_edge<<<NE / 128, 256>>>(z);
        k_gemm_proj<<<(PROJ_COLS / 128) * (NN / 128), 256>>>(s);
        k_pointify<<<(NN * 192) / 256, 256>>>(rot, trans);
        k_node<<<NN, 256>>>(mask, head_w, rot, trans);
        k_gemm_out<<<dim3(CS / 128, NN / 128), 256>>>(out_b, out);
    }
}

// round 14
// speedup vs baseline: 1.0834x; 1.0511x over previous
#include <cuda_runtime.h>
#include <cuda_fp16.h>
#include <math.h>

#define NN 8192
#define NE 262144
#define CS 384
#define CZ 128
#define CH 16
#define HH 12
#define PQK 4
#define PV 8
#define PROJ_COLS 1152      // 192 q | 384 kv | 144 qp | 432 kvp
#define EDGE_COLS 44        // 12 b | 32 pz
#define FEAT_COLS 960
#define S_QK 0.14433756729740643f
#define S_B  0.5773502691896258f
#define S_PT 0.1360827634879543f
#define INF_C 100000.0f
#define DN_FAST 128

// ---------------- scratch ----------------
__device__ float  g_proj[(size_t)NN * PROJ_COLS];
__device__ float  g_qpts[(size_t)NN * 144];
__device__ float  g_kpts[(size_t)NN * 144];
__device__ __half g_k16[(size_t)NN * 192];
__device__ __half g_v16[(size_t)NN * 192];
__device__ __half g_vpts16[(size_t)NN * 288];
__device__ __half g_pz16[(size_t)NE * 32];
__device__ float  g_bE[(size_t)NE * 12];
__device__ float  g_abuf[(size_t)NE * HH];
__device__ __align__(16) __half g_feats16[(size_t)NN * FEAT_COLS];
__device__ int    g_rank[NE];
__device__ int    g_dstOf[NE];
__device__ int    g_hist[NN];
__device__ int    g_off[NN + 1];
__device__ int    g_cursor[NN];
__device__ unsigned g_Wp16[(CS / 2) * PROJ_COLS];
__device__ unsigned g_We16[(CZ / 2) * EDGE_COLS];
__device__ unsigned g_Wo16[(FEAT_COLS / 2) * CS];
__device__ float    g_Bproj[PROJ_COLS];
__device__ float    g_Bedge[EDGE_COLS];

__device__ __forceinline__ unsigned pack_h2(float x, float y) {
    __half2 h = __floats2half2_rn(x, y);
    return *reinterpret_cast<unsigned*>(&h);
}

// ---------------- weight packing ----------------
#define SEG0 ((CS / 2) * PROJ_COLS)
#define SEG1 ((CZ / 2) * EDGE_COLS)
#define SEG2 ((FEAT_COLS / 2) * CS)
#define PACKP_TOTAL (SEG0 + PROJ_COLS)
#define PACKR_TOTAL (SEG1 + SEG2 + EDGE_COLS)

__device__ __forceinline__ float projw(int k, int col,
                                       const float* q_w, const float* kv_w,
                                       const float* qp_w, const float* kvp_w) {
    if (col < 192)  return q_w[k * 192 + col];
    if (col < 576)  return kv_w[k * 384 + (col - 192)];
    if (col < 720)  return qp_w[k * 144 + (col - 576)];
    return kvp_w[k * 432 + (col - 720)];
}

__global__ void k_pack_proj(const float* __restrict__ q_w, const float* __restrict__ q_b,
                            const float* __restrict__ kv_w, const float* __restrict__ kv_b,
                            const float* __restrict__ qp_w, const float* __restrict__ qp_b,
                            const float* __restrict__ kvp_w, const float* __restrict__ kvp_b) {
    int gid = blockIdx.x * blockDim.x + threadIdx.x;
    if (gid < SEG0) {
        int r2 = gid / PROJ_COLS, col = gid % PROJ_COLS;
        g_Wp16[gid] = pack_h2(projw(2 * r2, col, q_w, kv_w, qp_w, kvp_w),
                              projw(2 * r2 + 1, col, q_w, kv_w, qp_w, kvp_w));
    } else if (gid < PACKP_TOTAL) {
        int j = gid - SEG0;
        float v;
        if (j < 192)      v = q_b[j];
        else if (j < 576) v = kv_b[j - 192];
        else if (j < 720) v = qp_b[j - 576];
        else              v = kvp_b[j - 720];
        g_Bproj[j] = v;
    }
}

__global__ void k_pack_rest(const float* __restrict__ b_w, const float* __restrict__ b_b,
                            const float* __restrict__ dz_w, const float* __restrict__ dz_b,
                            const float* __restrict__ out_w) {
    int gid = blockIdx.x * blockDim.x + threadIdx.x;
    if (gid < SEG1) {
        int r2 = gid / EDGE_COLS, c = gid % EDGE_COLS;
        float v0 = (c < 12) ? b_w[(2 * r2) * 12 + c] : dz_w[(2 * r2) * 32 + (c - 12)];
        float v1 = (c < 12) ? b_w[(2 * r2 + 1) * 12 + c] : dz_w[(2 * r2 + 1) * 32 + (c - 12)];
        g_We16[gid] = pack_h2(v0, v1);
    } else if (gid < SEG1 + SEG2) {
        int j = gid - SEG1;
        int r2 = j / CS, c = j % CS;
        g_Wo16[j] = pack_h2(out_w[(size_t)(2 * r2) * CS + c],
                            out_w[(size_t)(2 * r2 + 1) * CS + c]);
    } else if (gid < PACKR_TOTAL) {
        int c = gid - SEG1 - SEG2;
        g_Bedge[c] = (c < 12) ? b_b[c] : dz_b[c - 12];
    }
}

// ---------------- sorting ----------------
__global__ void k_zero_hist() {
    int i = blockIdx.x * blockDim.x + threadIdx.x;
    if (i < NN) g_hist[i] = 0;
}
__global__ void k_hist(const int* __restrict__ edge_index) {
    int e = blockIdx.x * blockDim.x + threadIdx.x;
    if (e < NE) atomicAdd(&g_hist[edge_index[NE + e]], 1);
}
__global__ void k_scan() {
    __shared__ int wsum[32];
    int tid = threadIdx.x;
    int lane = tid & 31, wid = tid >> 5;
    int base = tid * 8;
    int local[8];
    int s = 0;
    #pragma unroll
    for (int i = 0; i < 8; i++) { local[i] = g_hist[base + i]; s += local[i]; }
    int v = s;
    #pragma unroll
    for (int d = 1; d < 32; d <<= 1) {
        int t = __shfl_up_sync(0xffffffffu, v, d);
        if (lane >= d) v += t;
    }
    if (lane == 31) wsum[wid] = v;
    __syncthreads();
    if (wid == 0) {
        int w = wsum[lane];
        #pragma unroll
        for (int d = 1; d < 32; d <<= 1) {
            int t = __shfl_up_sync(0xffffffffu, w, d);
            if (lane >= d) w += t;
        }
        wsum[lane] = w;
    }
    __syncthreads();
    int run = v - s + (wid > 0 ? wsum[wid - 1] : 0);
    #pragma unroll
    for (int i = 0; i < 8; i++) {
        g_off[base + i] = run;
        g_cursor[base + i] = run;
        run += local[i];
    }
    if (tid == 1023) g_off[NN] = run;
}
__global__ void k_scatter(const int* __restrict__ edge_index) {
    int e = blockIdx.x * blockDim.x + threadIdx.x;
    if (e >= NE) return;
    int src = edge_index[NE + e];
    int dst = edge_index[e];
    int pos = atomicAdd(&g_cursor[src], 1);
    g_rank[e] = pos;
    g_dstOf[pos] = dst;
}

// ---------------- fp16 mma helper ----------------
__device__ __forceinline__ void mma_f16(float* c, unsigned a0, unsigned a1, unsigned a2,
                                        unsigned a3, unsigned b0, unsigned b1) {
    asm volatile("mma.sync.aligned.m16n8k16.row.col.f32.f16.f16.f32 "
                 "{%0,%1,%2,%3}, {%4,%5,%6,%7}, {%8,%9}, {%0,%1,%2,%3};"
                 : "+f"(c[0]), "+f"(c[1]), "+f"(c[2]), "+f"(c[3])
                 : "r"(a0), "r"(a1), "r"(a2), "r"(a3), "r"(b0), "r"(b1));
}

#define AP2 136
#define BP2 136
#define EBP2 72
#define SMEM_ARENA 17408

__device__ __forceinline__ void proj_store2(int r, int col, float v0, float v1) {
    if (col >= 192 && col < 576) {
        int u = col - 192;
        int h = u >> 5, c = u & 31;
        __half2 hv = __floats2half2_rn(v0, v1);
        if (c < 16) *reinterpret_cast<__half2*>(&g_k16[(size_t)r * 192 + h * 16 + c]) = hv;
        else        *reinterpret_cast<__half2*>(&g_v16[(size_t)r * 192 + h * 16 + (c - 16)]) = hv;
    } else {
        float2 fv = make_float2(v0, v1);
        *reinterpret_cast<float2*>(&g_proj[(size_t)r * PROJ_COLS + col]) = fv;
    }
}

// ---------------- pipelined 128x128 fp16 GEMM ----------------
template <int N, int K, int MODE>
__device__ __forceinline__ void gemm128_f16(const void* __restrict__ Aptr,
                                            const unsigned* __restrict__ W16,
                                            const float* __restrict__ Bias,
                                            float* __restrict__ C,
                                            int row0, int col0, char* smemraw) {
    unsigned (*As)[8][AP2] = reinterpret_cast<unsigned (*)[8][AP2]>(smemraw);
    unsigned (*Bs)[8][BP2] = reinterpret_cast<unsigned (*)[8][BP2]>(smemraw + 2 * 8 * AP2 * 4);
    const float*  Af = (const float*)Aptr;
    const __half* Ah = (const __half*)Aptr;
    const int tid = threadIdx.x;
    const int lane = tid & 31, w = tid >> 5;
    const int gid = lane >> 2, tig = lane & 3;
    const int wm = (w & 1) * 64;
    const int wn = (w >> 1) * 32;

    float acc[4][4][4];
    #pragma unroll
    for (int mt = 0; mt < 4; mt++)
        #pragma unroll
        for (int nt = 0; nt < 4; nt++)
            #pragma unroll
            for (int i = 0; i < 4; i++) acc[mt][nt][i] = 0.f;

    float4 pa[2];
    uint4  pah;
    unsigned pb[4];

    if (MODE == 2) {
        int m = tid >> 1, k8 = (tid & 1) * 8;
        pah = *reinterpret_cast<const uint4*>(&Ah[(size_t)(row0 + m) * K + k8]);
    } else {
        #pragma unroll
        for (int l = 0; l < 2; l++) {
            int idx = tid + 256 * l;
            int m = idx >> 2, kq = (idx & 3) * 4;
            pa[l] = *reinterpret_cast<const float4*>(&Af[(size_t)(row0 + m) * K + kq]);
        }
    }
    #pragma unroll
    for (int l = 0; l < 4; l++) {
        int idx = tid + 256 * l;
        int r = idx >> 7, c = idx & 127;
        pb[l] = W16[(size_t)r * N + col0 + c];
    }
    if (MODE == 2) {
        int m = tid >> 1, k2 = (tid & 1) * 4;
        As[0][k2 + 0][m] = pah.x;
        As[0][k2 + 1][m] = pah.y;
        As[0][k2 + 2][m] = pah.z;
        As[0][k2 + 3][m] = pah.w;
    } else {
        #pragma unroll
        for (int l = 0; l < 2; l++) {
            int idx = tid + 256 * l;
            int m = idx >> 2, k2 = (idx & 3) * 2;
            As[0][k2 + 0][m] = pack_h2(pa[l].x, pa[l].y);
            As[0][k2 + 1][m] = pack_h2(pa[l].z, pa[l].w);
        }
    }
    #pragma unroll
    for (int l = 0; l < 4; l++) {
        int idx = tid + 256 * l;
        Bs[0][idx >> 7][idx & 127] = pb[l];
    }
    __syncthreads();

    const int nIter = K / 16;
    for (int it = 0; it < nIter; it++) {
        int buf = it & 1;
        if (it + 1 < nIter) {
            int k0 = (it + 1) * 16;
            if (MODE == 2) {
                int m = tid >> 1, k8 = (tid & 1) * 8;
                pah = *reinterpret_cast<const uint4*>(&Ah[(size_t)(row0 + m) * K + k0 + k8]);
            } else {
                #pragma unroll
                for (int l = 0; l < 2; l++) {
                    int idx = tid + 256 * l;
                    int m = idx >> 2, kq = (idx & 3) * 4;
                    pa[l] = *reinterpret_cast<const float4*>(&Af[(size_t)(row0 + m) * K + k0 + kq]);
                }
            }
            #pragma unroll
            for (int l = 0; l < 4; l++) {
                int idx = tid + 256 * l;
                int r = idx >> 7, c = idx & 127;
                pb[l] = W16[(size_t)(k0 / 2 + r) * N + col0 + c];
            }
        }
        {
            unsigned a[4][4], b[4][2];
            #pragma unroll
            for (int mt = 0; mt < 4; mt++) {
                int m0 = wm + mt * 16;
                a[mt][0] = As[buf][tig][m0 + gid];
                a[mt][1] = As[buf][tig][m0 + gid + 8];
                a[mt][2] = As[buf][tig + 4][m0 + gid];
                a[mt][3] = As[buf][tig + 4][m0 + gid + 8];
            }
            #pragma unroll
            for (int nt = 0; nt < 4; nt++) {
                int n0 = wn + nt * 8;
                b[nt][0] = Bs[buf][tig][n0 + gid];
                b[nt][1] = Bs[buf][tig + 4][n0 + gid];
            }
            #pragma unroll
            for (int mt = 0; mt < 4; mt++)
                #pragma unroll
                for (int nt = 0; nt < 4; nt++)
                    mma_f16(acc[mt][nt], a[mt][0], a[mt][1], a[mt][2], a[mt][3],
                            b[nt][0], b[nt][1]);
        }
        if (it + 1 < nIter) {
            int nb = 1 - buf;
            if (MODE == 2) {
                int m = tid >> 1, k2 = (tid & 1) * 4;
                As[nb][k2 + 0][m] = pah.x;
                As[nb][k2 + 1][m] = pah.y;
                As[nb][k2 + 2][m] = pah.z;
                As[nb][k2 + 3][m] = pah.w;
            } else {
                #pragma unroll
                for (int l = 0; l < 2; l++) {
                    int idx = tid + 256 * l;
                    int m = idx >> 2, k2 = (idx & 3) * 2;
                    As[nb][k2 + 0][m] = pack_h2(pa[l].x, pa[l].y);
                    As[nb][k2 + 1][m] = pack_h2(pa[l].z, pa[l].w);
                }
            }
            #pragma unroll
            for (int l = 0; l < 4; l++) {
                int idx = tid + 256 * l;
                Bs[nb][idx >> 7][idx & 127] = pb[l];
            }
        }
        __syncthreads();
    }
    #pragma unroll
    for (int mt = 0; mt < 4; mt++) {
        #pragma unroll
        for (int i = 0; i < 2; i++) {
            int r = row0 + wm + mt * 16 + gid + i * 8;
            #pragma unroll
            for (int nt = 0; nt < 4; nt++) {
                int cb = col0 + wn + nt * 8 + 2 * tig;
                float v0 = acc[mt][nt][i * 2 + 0] + Bias[cb + 0];
                float v1 = acc[mt][nt][i * 2 + 1] + Bias[cb + 1];
                if (MODE == 1) proj_store2(r, cb, v0, v1);
                else {
                    C[(size_t)r * N + cb]     = v0;
                    C[(size_t)r * N + cb + 1] = v1;
                }
            }
        }
    }
}

// ---------------- pipelined 128x64 fp16 edge GEMM ----------------
__device__ __forceinline__ void edge_gemm_f16(const float* __restrict__ A,
                                              const unsigned* __restrict__ W16,
                                              const float* __restrict__ Bias,
                                              const int* __restrict__ rowmap,
                                              int row0, char* smemraw) {
    unsigned (*As)[8][AP2] = reinterpret_cast<unsigned (*)[8][AP2]>(smemraw);
    unsigned (*Bs)[8][EBP2] = reinterpret_cast<unsigned (*)[8][EBP2]>(smemraw + 2 * 8 * AP2 * 4);
    const int tid = threadIdx.x;
    const int lane = tid & 31, w = tid >> 5;
    const int gid = lane >> 2, tig = lane & 3;
    const int wm = (w & 3) * 32;
    const int wn = (w >> 2) * 32;
    const int N = EDGE_COLS, K = CZ;

    float c[2][4][4];
    #pragma unroll
    for (int mt = 0; mt < 2; mt++)
        #pragma unroll
        for (int nt = 0; nt < 4; nt++)
            #pragma unroll
            for (int i = 0; i < 4; i++) c[mt][nt][i] = 0.f;

    float4 pa[2];
    unsigned pb[2];

    #pragma unroll
    for (int l = 0; l < 2; l++) {
        int idx = tid + 256 * l;
        int r = idx >> 2, kc = (idx & 3) * 4;
        pa[l] = *reinterpret_cast<const float4*>(&A[(size_t)(row0 + r) * K + kc]);
    }
    #pragma unroll
    for (int l = 0; l < 2; l++) {
        int idx = tid + 256 * l;
        int r = idx >> 6, cc = idx & 63;
        pb[l] = (cc < N) ? W16[(size_t)r * N + cc] : 0u;
    }
    #pragma unroll
    for (int l = 0; l < 2; l++) {
        int idx = tid + 256 * l;
        int r = idx >> 2, k2 = (idx & 3) * 2;
        As[0][k2 + 0][r] = pack_h2(pa[l].x, pa[l].y);
        As[0][k2 + 1][r] = pack_h2(pa[l].z, pa[l].w);
    }
    #pragma unroll
    for (int l = 0; l < 2; l++) {
        int idx = tid + 256 * l;
        Bs[0][idx >> 6][idx & 63] = pb[l];
    }
    __syncthreads();

    const int nIter = K / 16;
    for (int it = 0; it < nIter; it++) {
        int buf = it & 1;
        if (it + 1 < nIter) {
            int k0 = (it + 1) * 16;
            #pragma unroll
            for (int l = 0; l < 2; l++) {
                int idx = tid + 256 * l;
                int r = idx >> 2, kc = (idx & 3) * 4;
                pa[l] = *reinterpret_cast<const float4*>(&A[(size_t)(row0 + r) * K + k0 + kc]);
            }
            #pragma unroll
            for (int l = 0; l < 2; l++) {
                int idx = tid + 256 * l;
                int r = idx >> 6, cc = idx & 63;
                pb[l] = (cc < N) ? W16[(size_t)(k0 / 2 + r) * N + cc] : 0u;
            }
        }
        {
            unsigned a[2][4], b[4][2];
            #pragma unroll
            for (int mt = 0; mt < 2; mt++) {
                int m0 = wm + mt * 16;
                a[mt][0] = As[buf][tig][m0 + gid];
                a[mt][1] = As[buf][tig][m0 + gid + 8];
                a[mt][2] = As[buf][tig + 4][m0 + gid];
                a[mt][3] = As[buf][tig + 4][m0 + gid + 8];
            }
            #pragma unroll
            for (int nt = 0; nt < 4; nt++) {
                int n0 = wn + nt * 8;
                b[nt][0] = Bs[buf][tig][n0 + gid];
                b[nt][1] = Bs[buf][tig + 4][n0 + gid];
            }
            #pragma unroll
            for (int mt = 0; mt < 2; mt++)
                #pragma unroll
                for (int nt = 0; nt < 4; nt++)
                    mma_f16(c[mt][nt], a[mt][0], a[mt][1], a[mt][2], a[mt][3],
                            b[nt][0], b[nt][1]);
        }
        if (it + 1 < nIter) {
            int nb = 1 - buf;
            #pragma unroll
            for (int l = 0; l < 2; l++) {
                int idx = tid + 256 * l;
                int r = idx >> 2, k2 = (idx & 3) * 2;
                As[nb][k2 + 0][r] = pack_h2(pa[l].x, pa[l].y);
                As[nb][k2 + 1][r] = pack_h2(pa[l].z, pa[l].w);
            }
            #pragma unroll
            for (int l = 0; l < 2; l++) {
                int idx = tid + 256 * l;
                Bs[nb][idx >> 6][idx & 63] = pb[l];
            }
        }
        __syncthreads();
    }
    #pragma unroll
    for (int mt = 0; mt < 2; mt++) {
        #pragma unroll
        for (int i = 0; i < 2; i++) {
            int r = row0 + wm + mt * 16 + gid + i * 8;
            int crow = rowmap[r];
            #pragma unroll
            for (int nt = 0; nt < 4; nt++) {
                int cbase = wn + nt * 8 + 2 * tig;
                #pragma unroll
                for (int j = 0; j < 2; j++) {
                    int cc = cbase + j;
                    if (cc < N) {
                        float val = c[mt][nt][i * 2 + j] + Bias[cc];
                        if (cc < 12) g_bE[(size_t)crow * 12 + cc] = val;
                        else         g_pz16[(size_t)crow * 32 + (cc - 12)] = __float2half(val);
                    }
                }
            }
        }
    }
}

__global__ __launch_bounds__(256, 2) void k_gemm_proj(const float* __restrict__ s) {
    __shared__ __align__(16) char smemraw[SMEM_ARENA];
    int b = blockIdx.x;
    gemm128_f16<PROJ_COLS, CS, 1>(s, g_Wp16, g_Bproj, nullptr,
                                  (b / 9) * 128, (b % 9) * 128, smemraw);
}
__global__ __launch_bounds__(256, 2) void k_gemm_edge(const float* __restrict__ z) {
    __shared__ __align__(16) char smemraw[SMEM_ARENA];
    edge_gemm_f16(z, g_We16, g_Bedge, g_rank, blockIdx.x * 128, smemraw);
}
__global__ __launch_bounds__(256, 2) void k_gemm_out(const float* __restrict__ out_b,
                                                     float* __restrict__ out) {
    __shared__ __align__(16) char smemraw[SMEM_ARENA];
    gemm128_f16<CS, FEAT_COLS, 2>(g_feats16, g_Wo16, out_b, out,
                                  blockIdx.y * 128, blockIdx.x * 128, smemraw);
}

// ---------------- point transform ----------------
__global__ void k_pointify(const float* __restrict__ rot, const float* __restrict__ trans) {
    int gid = blockIdx.x * blockDim.x + threadIdx.x;
    if (gid >= NN * 192) return;
    int n = gid / 192;
    int p_all = gid % 192;
    const float* R = rot + (size_t)n * 9;
    const float* T = trans + (size_t)n * 3;
    const float* pr = g_proj + (size_t)n * PROJ_COLS;
    if (p_all < 48) {
        int p = p_all;
        float y0 = pr[576 + 0 * 48 + p];
        float y1 = pr[576 + 1 * 48 + p];
        float y2 = pr[576 + 2 * 48 + p];
        #pragma unroll
        for (int i = 0; i < 3; i++) {
            float v = R[i * 3 + 0] * y0 + R[i * 3 + 1] * y1 + R[i * 3 + 2] * y2 + T[i];
            g_qpts[((size_t)n * 48 + p) * 3 + i] = v;
        }
    } else {
        int p = p_all - 48;
        float y0 = pr[720 + 0 * 144 + p];
        float y1 = pr[720 + 1 * 144 + p];
        float y2 = pr[720 + 2 * 144 + p];
        int h = p / 12, j = p % 12;
        #pragma unroll
        for (int i = 0; i < 3; i++) {
            float v = R[i * 3 + 0] * y0 + R[i * 3 + 1] * y1 + R[i * 3 + 2] * y2 + T[i];
            if (j < PQK) g_kpts[((size_t)n * 48 + h * 4 + j) * 3 + i] = v;
            else         g_vpts16[(size_t)n * 288 + (h * 8 + (j - 4)) * 3 + i] = __float2half(v);
        }
    }
}

// ---------------- fused per-node: logits + softmax + aggregation ----------------
__device__ __forceinline__ float4 h4_to_f4(uint2 u) {
    __half2* hp = reinterpret_cast<__half2*>(&u);
    float2 f0 = __half22float2(hp[0]);
    float2 f1 = __half22float2(hp[1]);
    return make_float4(f0.x, f0.y, f1.x, f1.y);
}

template <bool FAST>
__device__ __forceinline__ void node_body(
    int n, int tid, int beg, int dn,
    const float* __restrict__ mask, const float* __restrict__ head_weights,
    const float* __restrict__ rot, const float* __restrict__ trans,
    float4* s_q, float4* s_qp, float* s_hw, float* s_logit, int* s_dst, float* s_msk,
    float* s_red, float* s_amax, float* s_inv, float* sacc, float* s_pt2) {

    const float4* proj4 = reinterpret_cast<const float4*>(g_proj);
    const float4* kpts4 = reinterpret_cast<const float4*>(g_kpts);

    float* lb = FAST ? s_logit : (g_abuf + (size_t)beg * HH);
    const int* dl = FAST ? s_dst : (g_dstOf + beg);

    if (tid < 48) s_q[tid] = proj4[(size_t)n * 288 + tid];
    else if (tid < 84) s_qp[tid - 48] = reinterpret_cast<const float4*>(g_qpts)[(size_t)n * 36 + (tid - 48)];
    else if (tid < 96) s_hw[tid - 84] = 0.5f * S_PT * log1pf(expf(head_weights[tid - 84]));
    if (FAST) {
        for (int i = tid; i < dn; i += 256) {
            int d = g_dstOf[beg + i];
            s_dst[i] = d;
            s_msk[i] = mask[d];
        }
    }
    __syncthreads();

    float mn = mask[n];

    if (tid < 252) {
        int h = tid % HH;
        float4 q0 = s_q[h * 4 + 0], q1 = s_q[h * 4 + 1], q2 = s_q[h * 4 + 2], q3 = s_q[h * 4 + 3];
        float4 p0 = s_qp[h * 3 + 0], p1 = s_qp[h * 3 + 1], p2 = s_qp[h * 3 + 2];
        float hwv = s_hw[h];
        for (int i = tid / HH; i < dn; i += 21) {
            int dst = dl[i];
            const uint4* kh = reinterpret_cast<const uint4*>(g_k16 + (size_t)dst * 192 + h * 16);
            uint4 u0 = kh[0], u1 = kh[1];
            __half2* h0 = reinterpret_cast<__half2*>(&u0);
            __half2* h1 = reinterpret_cast<__half2*>(&u1);
            float2 f0 = __half22float2(h0[0]), f1 = __half22float2(h0[1]);
            float2 f2 = __half22float2(h0[2]), f3 = __half22float2(h0[3]);
            float2 f4 = __half22float2(h1[0]), f5 = __half22float2(h1[1]);
            float2 f6 = __half22float2(h1[2]), f7 = __half22float2(h1[3]);
            float dot = q0.x * f0.x + q0.y * f0.y + q0.z * f1.x + q0.w * f1.y
                      + q1.x * f2.x + q1.y * f2.y + q1.z * f3.x + q1.w * f3.y
                      + q2.x * f4.x + q2.y * f4.y + q2.z * f5.x + q2.w * f5.y
                      + q3.x * f6.x + q3.y * f6.y + q3.z * f7.x + q3.w * f7.y;
            const float4* kp = kpts4 + (size_t)dst * 36 + h * 3;
            float4 d0 = kp[0], d1 = kp[1], d2 = kp[2];
            float pt = 0.f;
            pt += (p0.x - d0.x) * (p0.x - d0.x) + (p0.y - d0.y) * (p0.y - d0.y)
                + (p0.z - d0.z) * (p0.z - d0.z) + (p0.w - d0.w) * (p0.w - d0.w);
            pt += (p1.x - d1.x) * (p1.x - d1.x) + (p1.y - d1.y) * (p1.y - d1.y)
                + (p1.z - d1.z) * (p1.z - d1.z) + (p1.w - d1.w) * (p1.w - d1.w);
            pt += (p2.x - d2.x) * (p2.x - d2.x) + (p2.y - d2.y) * (p2.y - d2.y)
                + (p2.z - d2.z) * (p2.z - d2.z) + (p2.w - d2.w) * (p2.w - d2.w);
            float b = g_bE[(size_t)(beg + i) * 12 + h];
            float mk = FAST ? s_msk[i] : mask[dst];
            float em = INF_C * (mk * mn - 1.f);
            lb[i * HH + h] = dot * S_QK + S_B * b - hwv * pt + em;
        }
    }
    __syncthreads();

    if (tid < 96) {
        int h = tid % HH, j = tid / HH;
        float m = -INFINITY;
        for (int i = j; i < dn; i += 8) m = fmaxf(m, lb[i * HH + h]);
        s_red[tid] = m;
    }
    __syncthreads();
    if (tid < HH) {
        float m = -INFINITY;
        #pragma unroll
        for (int j = 0; j < 8; j++) m = fmaxf(m, s_red[j * HH + tid]);
        if (!isfinite(m)) m = 0.f;
        s_amax[tid] = m;
    }
    __syncthreads();
    if (tid < 96) {
        int h = tid % HH, j = tid / HH;
        float am = s_amax[h];
        float s = 0.f;
        for (int i = j; i < dn; i += 8) s += expf(lb[i * HH + h] - am);
        s_red[tid] = s;
    }
    __syncthreads();
    if (tid < HH) {
        float s = 0.f;
        #pragma unroll
        for (int j = 0; j < 8; j++) s += s_red[j * HH + tid];
        s_inv[tid] = 1.f / (s + 1e-16f);
    }
    __syncthreads();

    for (int idx = tid; idx < dn * HH; idx += 256) {
        int h = idx % HH;
        lb[idx] = expf(lb[idx] - s_amax[h]) * s_inv[h];
    }
    __syncthreads();

    if (tid < 144) {
        int chunk = tid / 72;
        int c = tid % 72;
        int h = c / 6;
        float4 acc = {0.f, 0.f, 0.f, 0.f};
        #pragma unroll 8
        for (int i = chunk; i < dn; i += 2) {
            int dst = dl[i];
            float w = lb[i * HH + h];
            float4 v = h4_to_f4(*reinterpret_cast<const uint2*>(g_vpts16 + (size_t)dst * 288 + c * 4));
            acc.x += w * v.x; acc.y += w * v.y; acc.z += w * v.z; acc.w += w * v.w;
        }
        float* dstp = (chunk == 0) ? (sacc + 192 + c * 4) : (s_pt2 + c * 4);
        dstp[0] = acc.x; dstp[1] = acc.y; dstp[2] = acc.z; dstp[3] = acc.w;
    } else if (tid >= 160 && tid < 208) {
        int c = tid - 160;
        int h = c >> 2, c4 = c & 3;
        float4 acc = {0.f, 0.f, 0.f, 0.f};
        #pragma unroll 8
        for (int i = 0; i < dn; i++) {
            int dst = dl[i];
            float w = lb[i * HH + h];
            float4 v = h4_to_f4(*reinterpret_cast<const uint2*>(g_v16 + (size_t)dst * 192 + h * 16 + c4 * 4));
            acc.x += w * v.x; acc.y += w * v.y; acc.z += w * v.z; acc.w += w * v.w;
        }
        sacc[c * 4 + 0] = acc.x; sacc[c * 4 + 1] = acc.y;
        sacc[c * 4 + 2] = acc.z; sacc[c * 4 + 3] = acc.w;
    } else if (tid >= 224 && tid < 248) {
        int c = tid - 224;
        int j = c & 7, hq = c >> 3;
        float4 acc[4];
        #pragma unroll
        for (int r = 0; r < 4; r++) acc[r] = make_float4(0.f, 0.f, 0.f, 0.f);
        #pragma unroll 8
        for (int i = 0; i < dn; i++) {
            float4 p = h4_to_f4(*reinterpret_cast<const uint2*>(g_pz16 + (size_t)(beg + i) * 32 + j * 4));
            #pragma unroll
            for (int r = 0; r < 4; r++) {
                float w = lb[i * HH + hq * 4 + r];
                acc[r].x += w * p.x; acc[r].y += w * p.y;
                acc[r].z += w * p.z; acc[r].w += w * p.w;
            }
        }
        #pragma unroll
        for (int r = 0; r < 4; r++) {
            int base = 480 + (hq * 4 + r) * 32 + j * 4;
            sacc[base + 0] = acc[r].x; sacc[base + 1] = acc[r].y;
            sacc[base + 2] = acc[r].z; sacc[base + 3] = acc[r].w;
        }
    }
    __syncthreads();
    for (int t = tid; t < 288; t += 256) sacc[192 + t] += s_pt2[t];
    __syncthreads();

    __half* f = g_feats16 + (size_t)n * FEAT_COLS;
    if (tid < 192) f[tid] = __float2half(sacc[tid]);
    for (int t = tid; t < 384; t += 256) f[576 + t] = __float2half(sacc[480 + t]);
    if (tid < 96) {
        int q = tid;
        float g0 = sacc[192 + q * 3 + 0] - trans[(size_t)n * 3 + 0];
        float g1 = sacc[192 + q * 3 + 1] - trans[(size_t)n * 3 + 1];
        float g2 = sacc[192 + q * 3 + 2] - trans[(size_t)n * 3 + 2];
        const float* R = rot + (size_t)n * 9;
        float l0 = R[0] * g0 + R[3] * g1 + R[6] * g2;
        float l1 = R[1] * g0 + R[4] * g1 + R[7] * g2;
        float l2 = R[2] * g0 + R[5] * g1 + R[8] * g2;
        f[192 + q] = __float2half(l0);
        f[288 + q] = __float2half(l1);
        f[384 + q] = __float2half(l2);
        f[480 + q] = __float2half(sqrtf(l0 * l0 + l1 * l1 + l2 * l2 + 1e-8f));
    }
}

__global__ void k_node(const float* __restrict__ mask, const float* __restrict__ head_weights,
                       const float* __restrict__ rot, const float* __restrict__ trans) {
    __shared__ float4 s_q[48];
    __shared__ float4 s_qp[36];
    __shared__ float  s_hw[12];
    __shared__ float  s_logit[DN_FAST * HH];
    __shared__ int    s_dst[DN_FAST];
    __shared__ float  s_msk[DN_FAST];
    __shared__ float  s_red[96];
    __shared__ float  s_amax[HH], s_inv[HH];
    __shared__ float  sacc[864];
    __shared__ float  s_pt2[288];

    int n = blockIdx.x;
    int tid = threadIdx.x;
    int beg = g_off[n], dn = g_off[n + 1] - beg;

    if (dn <= DN_FAST)
        node_body<true>(n, tid, beg, dn, mask, head_weights, rot, trans,
                        s_q, s_qp, s_hw, s_logit, s_dst, s_msk, s_red, s_amax, s_inv, sacc, s_pt2);
    else
        node_body<false>(n, tid, beg, dn, mask, head_weights, rot, trans,
                         s_q, s_qp, s_hw, s_logit, s_dst, s_msk, s_red, s_amax, s_inv, sacc, s_pt2);
}

// ---------------- launch ----------------
extern "C" void kernel_launch(void* const* d_in, const int* in_sizes, int n_in,
                              void* d_out, int out_size) {
    const float* s          = (const float*)d_in[0];
    const float* z          = (const float*)d_in[1];
    const int*   edge_index = (const int*)  d_in[2];
    const float* rot        = (const float*)d_in[3];
    const float* trans      = (const float*)d_in[4];
    const float* mask       = (const float*)d_in[5];
    const float* q_w        = (const float*)d_in[6];
    const float* q_b        = (const float*)d_in[7];
    const float* kv_w       = (const float*)d_in[8];
    const float* kv_b       = (const float*)d_in[9];
    const float* qp_w       = (const float*)d_in[10];
    const float* qp_b       = (const float*)d_in[11];
    const float* kvp_w      = (const float*)d_in[12];
    const float* kvp_b      = (const float*)d_in[13];
    const float* b_w        = (const float*)d_in[14];
    const float* b_b        = (const float*)d_in[15];
    const float* dz_w       = (const float*)d_in[16];
    const float* dz_b       = (const float*)d_in[17];
    const float* head_w     = (const float*)d_in[18];
    const float* out_w      = (const float*)d_in[19];
    const float* out_b      = (const float*)d_in[20];
    float* out = (float*)d_out;

    static cudaStream_t s2;
    static cudaEvent_t ev0, ev2;
    static int inited = 0;
    static bool streamsOK = false;
    if (!inited) {
        inited = 1;
        streamsOK =
            cudaStreamCreateWithFlags(&s2, cudaStreamNonBlocking) == cudaSuccess &&
            cudaEventCreateWithFlags(&ev0, cudaEventDisableTiming) == cudaSuccess &&
            cudaEventCreateWithFlags(&ev2, cudaEventDisableTiming) == cudaSuccess;
    }

    if (streamsOK) {
        cudaEventRecord(ev0, 0);
        cudaStreamWaitEvent(s2, ev0, 0);
        k_zero_hist<<<NN / 256, 256, 0, s2>>>();
        k_hist<<<NE / 256, 256, 0, s2>>>(edge_index);
        k_scan<<<1, 1024, 0, s2>>>();
        k_scatter<<<NE / 256, 256, 0, s2>>>(edge_index);
        k_pack_rest<<<(PACKR_TOTAL + 255) / 256, 256, 0, s2>>>(b_w, b_b, dz_w, dz_b, out_w);
        k_gemm_edge<<<NE / 128, 256, 0, s2>>>(z);
        cudaEventRecord(ev2, s2);

        k_pack_proj<<<(PACKP_TOTAL + 255) / 256, 256>>>(q_w, q_b, kv_w, kv_b,
                                                        qp_w, qp_b, kvp_w, kvp_b);
        k_gemm_proj<<<(PROJ_COLS / 128) * (NN / 128), 256>>>(s);
        k_pointify<<<(NN * 192) / 256, 256>>>(rot, trans);

        cudaStreamWaitEvent(0, ev2, 0);
        k_node<<<NN, 256>>>(mask, head_w, rot, trans);
        k_gemm_out<<<dim3(CS / 128, NN / 128), 256>>>(out_b, out);
    } else {
        k_pack_proj<<<(PACKP_TOTAL + 255) / 256, 256>>>(q_w, q_b, kv_w, kv_b,
                                                        qp_w, qp_b, kvp_w, kvp_b);
        k_pack_rest<<<(PACKR_TOTAL + 255) / 256, 256>>>(b_w, b_b, dz_w, dz_b, out_w);
        k_zero_hist<<<NN / 256, 256>>>();
        k_hist<<<NE / 256, 256>>>(edge_index);
        k_scan<<<1, 1024>>>();
        k_scatter<<<NE / 256, 256>>>(edge_index);
        k_gemm_edge<<<NE / 128, 256>>>(z);
        k_gemm_proj<<<(PROJ_COLS / 128) * (NN / 128), 256>>>(s);
        k_pointify<<<(NN * 192) / 256, 256>>>(rot, trans);
        k_node<<<NN, 256>>>(mask, head_w, rot, trans);
        k_gemm_out<<<dim3(CS / 128, NN / 128), 256>>>(out_b, out);
    }
}

// round 15
// speedup vs baseline: 1.1062x; 1.0211x over previous
#include <cuda_runtime.h>
#include <cuda_fp16.h>
#include <math.h>

#define NN 8192
#define NE 262144
#define CS 384
#define CZ 128
#define CH 16
#define HH 12
#define PQK 4
#define PV 8
#define PROJ_COLS 1152      // 192 q | 384 kv | 144 qp | 432 kvp
#define EDGE_COLS 44        // 12 b | 32 pz
#define FEAT_COLS 960
#define S_QK 0.14433756729740643f
#define S_B  0.5773502691896258f
#define S_PT 0.1360827634879543f
#define INF_C 100000.0f
#define DN_FAST 128

// ---------------- scratch ----------------
__device__ float  g_proj[(size_t)NN * PROJ_COLS];
__device__ float  g_qpts[(size_t)NN * 144];
__device__ float  g_kpts[(size_t)NN * 144];
__device__ __half g_k16[(size_t)NN * 192];
__device__ __half g_v16[(size_t)NN * 192];
__device__ __half g_vpts16[(size_t)NN * 288];
__device__ __half g_pz16[(size_t)NE * 32];
__device__ float  g_bE[(size_t)NE * 12];
__device__ float  g_abuf[(size_t)NE * HH];
__device__ __align__(16) __half g_feats16[(size_t)NN * FEAT_COLS];
__device__ int    g_rank[NE];
__device__ int    g_dstOf[NE];
__device__ int    g_hist[NN];
__device__ int    g_off[NN + 1];
__device__ int    g_cursor[NN];
__device__ unsigned g_Wp16[(CS / 2) * PROJ_COLS];
__device__ unsigned g_We16[(CZ / 2) * EDGE_COLS];
__device__ unsigned g_Wo16[(FEAT_COLS / 2) * CS];
__device__ float    g_Bproj[PROJ_COLS];
__device__ float    g_Bedge[EDGE_COLS];

__device__ __forceinline__ unsigned pack_h2(float x, float y) {
    __half2 h = __floats2half2_rn(x, y);
    return *reinterpret_cast<unsigned*>(&h);
}

// ---------------- weight packing ----------------
#define SEG0 ((CS / 2) * PROJ_COLS)
#define SEG1 ((CZ / 2) * EDGE_COLS)
#define SEG2 ((FEAT_COLS / 2) * CS)
#define PACKP_TOTAL (SEG0 + PROJ_COLS)
#define PACKR_TOTAL (SEG1 + SEG2 + EDGE_COLS)

__device__ __forceinline__ float projw(int k, int col,
                                       const float* q_w, const float* kv_w,
                                       const float* qp_w, const float* kvp_w) {
    if (col < 192)  return q_w[k * 192 + col];
    if (col < 576)  return kv_w[k * 384 + (col - 192)];
    if (col < 720)  return qp_w[k * 144 + (col - 576)];
    return kvp_w[k * 432 + (col - 720)];
}

__global__ void k_pack_proj(const float* __restrict__ q_w, const float* __restrict__ q_b,
                            const float* __restrict__ kv_w, const float* __restrict__ kv_b,
                            const float* __restrict__ qp_w, const float* __restrict__ qp_b,
                            const float* __restrict__ kvp_w, const float* __restrict__ kvp_b) {
    int gid = blockIdx.x * blockDim.x + threadIdx.x;
    if (gid < SEG0) {
        int r2 = gid / PROJ_COLS, col = gid % PROJ_COLS;
        g_Wp16[gid] = pack_h2(projw(2 * r2, col, q_w, kv_w, qp_w, kvp_w),
                              projw(2 * r2 + 1, col, q_w, kv_w, qp_w, kvp_w));
    } else if (gid < PACKP_TOTAL) {
        int j = gid - SEG0;
        float v;
        if (j < 192)      v = q_b[j];
        else if (j < 576) v = kv_b[j - 192];
        else if (j < 720) v = qp_b[j - 576];
        else              v = kvp_b[j - 720];
        g_Bproj[j] = v;
    }
}

__global__ void k_pack_rest(const float* __restrict__ b_w, const float* __restrict__ b_b,
                            const float* __restrict__ dz_w, const float* __restrict__ dz_b,
                            const float* __restrict__ out_w) {
    int gid = blockIdx.x * blockDim.x + threadIdx.x;
    if (gid < SEG1) {
        int r2 = gid / EDGE_COLS, c = gid % EDGE_COLS;
        float v0 = (c < 12) ? b_w[(2 * r2) * 12 + c] : dz_w[(2 * r2) * 32 + (c - 12)];
        float v1 = (c < 12) ? b_w[(2 * r2 + 1) * 12 + c] : dz_w[(2 * r2 + 1) * 32 + (c - 12)];
        g_We16[gid] = pack_h2(v0, v1);
    } else if (gid < SEG1 + SEG2) {
        int j = gid - SEG1;
        int r2 = j / CS, c = j % CS;
        g_Wo16[j] = pack_h2(out_w[(size_t)(2 * r2) * CS + c],
                            out_w[(size_t)(2 * r2 + 1) * CS + c]);
    } else if (gid < PACKR_TOTAL) {
        int c = gid - SEG1 - SEG2;
        g_Bedge[c] = (c < 12) ? b_b[c] : dz_b[c - 12];
    }
}

// ---------------- sorting ----------------
__global__ void k_zero_hist() {
    int i = blockIdx.x * blockDim.x + threadIdx.x;
    if (i < NN) g_hist[i] = 0;
}
__global__ void k_hist(const int* __restrict__ edge_index) {
    int e = blockIdx.x * blockDim.x + threadIdx.x;
    if (e < NE) atomicAdd(&g_hist[edge_index[NE + e]], 1);
}
__global__ void k_scan() {
    __shared__ int wsum[32];
    int tid = threadIdx.x;
    int lane = tid & 31, wid = tid >> 5;
    int base = tid * 8;
    int local[8];
    int s = 0;
    #pragma unroll
    for (int i = 0; i < 8; i++) { local[i] = g_hist[base + i]; s += local[i]; }
    int v = s;
    #pragma unroll
    for (int d = 1; d < 32; d <<= 1) {
        int t = __shfl_up_sync(0xffffffffu, v, d);
        if (lane >= d) v += t;
    }
    if (lane == 31) wsum[wid] = v;
    __syncthreads();
    if (wid == 0) {
        int w = wsum[lane];
        #pragma unroll
        for (int d = 1; d < 32; d <<= 1) {
            int t = __shfl_up_sync(0xffffffffu, w, d);
            if (lane >= d) w += t;
        }
        wsum[lane] = w;
    }
    __syncthreads();
    int run = v - s + (wid > 0 ? wsum[wid - 1] : 0);
    #pragma unroll
    for (int i = 0; i < 8; i++) {
        g_off[base + i] = run;
        g_cursor[base + i] = run;
        run += local[i];
    }
    if (tid == 1023) g_off[NN] = run;
}
__global__ void k_scatter(const int* __restrict__ edge_index) {
    int e = blockIdx.x * blockDim.x + threadIdx.x;
    if (e >= NE) return;
    int src = edge_index[NE + e];
    int dst = edge_index[e];
    int pos = atomicAdd(&g_cursor[src], 1);
    g_rank[e] = pos;
    g_dstOf[pos] = dst;
}

// ---------------- fp16 mma helper ----------------
__device__ __forceinline__ void mma_f16(float* c, unsigned a0, unsigned a1, unsigned a2,
                                        unsigned a3, unsigned b0, unsigned b1) {
    asm volatile("mma.sync.aligned.m16n8k16.row.col.f32.f16.f16.f32 "
                 "{%0,%1,%2,%3}, {%4,%5,%6,%7}, {%8,%9}, {%0,%1,%2,%3};"
                 : "+f"(c[0]), "+f"(c[1]), "+f"(c[2]), "+f"(c[3])
                 : "r"(a0), "r"(a1), "r"(a2), "r"(a3), "r"(b0), "r"(b1));
}

#define AP2 136
#define BP2 136
#define EBP2 72
#define SMEM_ARENA 17408

__device__ __forceinline__ void proj_store2(int r, int col, float v0, float v1) {
    if (col >= 192 && col < 576) {
        int u = col - 192;
        int h = u >> 5, c = u & 31;
        __half2 hv = __floats2half2_rn(v0, v1);
        if (c < 16) *reinterpret_cast<__half2*>(&g_k16[(size_t)r * 192 + h * 16 + c]) = hv;
        else        *reinterpret_cast<__half2*>(&g_v16[(size_t)r * 192 + h * 16 + (c - 16)]) = hv;
    } else {
        float2 fv = make_float2(v0, v1);
        *reinterpret_cast<float2*>(&g_proj[(size_t)r * PROJ_COLS + col]) = fv;
    }
}

// ---------------- pipelined 128x128 fp16 GEMM ----------------
template <int N, int K, int MODE>
__device__ __forceinline__ void gemm128_f16(const void* __restrict__ Aptr,
                                            const unsigned* __restrict__ W16,
                                            const float* __restrict__ Bias,
                                            float* __restrict__ C,
                                            int row0, int col0, char* smemraw) {
    unsigned (*As)[8][AP2] = reinterpret_cast<unsigned (*)[8][AP2]>(smemraw);
    unsigned (*Bs)[8][BP2] = reinterpret_cast<unsigned (*)[8][BP2]>(smemraw + 2 * 8 * AP2 * 4);
    const float*  Af = (const float*)Aptr;
    const __half* Ah = (const __half*)Aptr;
    const int tid = threadIdx.x;
    const int lane = tid & 31, w = tid >> 5;
    const int gid = lane >> 2, tig = lane & 3;
    const int wm = (w & 1) * 64;
    const int wn = (w >> 1) * 32;

    float acc[4][4][4];
    #pragma unroll
    for (int mt = 0; mt < 4; mt++)
        #pragma unroll
        for (int nt = 0; nt < 4; nt++)
            #pragma unroll
            for (int i = 0; i < 4; i++) acc[mt][nt][i] = 0.f;

    float4 pa[2];
    uint4  pah;
    unsigned pb[4];

    if (MODE == 2) {
        int m = tid >> 1, k8 = (tid & 1) * 8;
        pah = *reinterpret_cast<const uint4*>(&Ah[(size_t)(row0 + m) * K + k8]);
    } else {
        #pragma unroll
        for (int l = 0; l < 2; l++) {
            int idx = tid + 256 * l;
            int m = idx >> 2, kq = (idx & 3) * 4;
            pa[l] = *reinterpret_cast<const float4*>(&Af[(size_t)(row0 + m) * K + kq]);
        }
    }
    #pragma unroll
    for (int l = 0; l < 4; l++) {
        int idx = tid + 256 * l;
        int r = idx >> 7, c = idx & 127;
        pb[l] = W16[(size_t)r * N + col0 + c];
    }
    if (MODE == 2) {
        int m = tid >> 1, k2 = (tid & 1) * 4;
        As[0][k2 + 0][m] = pah.x;
        As[0][k2 + 1][m] = pah.y;
        As[0][k2 + 2][m] = pah.z;
        As[0][k2 + 3][m] = pah.w;
    } else {
        #pragma unroll
        for (int l = 0; l < 2; l++) {
            int idx = tid + 256 * l;
            int m = idx >> 2, k2 = (idx & 3) * 2;
            As[0][k2 + 0][m] = pack_h2(pa[l].x, pa[l].y);
            As[0][k2 + 1][m] = pack_h2(pa[l].z, pa[l].w);
        }
    }
    #pragma unroll
    for (int l = 0; l < 4; l++) {
        int idx = tid + 256 * l;
        Bs[0][idx >> 7][idx & 127] = pb[l];
    }
    __syncthreads();

    const int nIter = K / 16;
    for (int it = 0; it < nIter; it++) {
        int buf = it & 1;
        if (it + 1 < nIter) {
            int k0 = (it + 1) * 16;
            if (MODE == 2) {
                int m = tid >> 1, k8 = (tid & 1) * 8;
                pah = *reinterpret_cast<const uint4*>(&Ah[(size_t)(row0 + m) * K + k0 + k8]);
            } else {
                #pragma unroll
                for (int l = 0; l < 2; l++) {
                    int idx = tid + 256 * l;
                    int m = idx >> 2, kq = (idx & 3) * 4;
                    pa[l] = *reinterpret_cast<const float4*>(&Af[(size_t)(row0 + m) * K + k0 + kq]);
                }
            }
            #pragma unroll
            for (int l = 0; l < 4; l++) {
                int idx = tid + 256 * l;
                int r = idx >> 7, c = idx & 127;
                pb[l] = W16[(size_t)(k0 / 2 + r) * N + col0 + c];
            }
        }
        {
            unsigned a[4][4], b[4][2];
            #pragma unroll
            for (int mt = 0; mt < 4; mt++) {
                int m0 = wm + mt * 16;
                a[mt][0] = As[buf][tig][m0 + gid];
                a[mt][1] = As[buf][tig][m0 + gid + 8];
                a[mt][2] = As[buf][tig + 4][m0 + gid];
                a[mt][3] = As[buf][tig + 4][m0 + gid + 8];
            }
            #pragma unroll
            for (int nt = 0; nt < 4; nt++) {
                int n0 = wn + nt * 8;
                b[nt][0] = Bs[buf][tig][n0 + gid];
                b[nt][1] = Bs[buf][tig + 4][n0 + gid];
            }
            #pragma unroll
            for (int mt = 0; mt < 4; mt++)
                #pragma unroll
                for (int nt = 0; nt < 4; nt++)
                    mma_f16(acc[mt][nt], a[mt][0], a[mt][1], a[mt][2], a[mt][3],
                            b[nt][0], b[nt][1]);
        }
        if (it + 1 < nIter) {
            int nb = 1 - buf;
            if (MODE == 2) {
                int m = tid >> 1, k2 = (tid & 1) * 4;
                As[nb][k2 + 0][m] = pah.x;
                As[nb][k2 + 1][m] = pah.y;
                As[nb][k2 + 2][m] = pah.z;
                As[nb][k2 + 3][m] = pah.w;
            } else {
                #pragma unroll
                for (int l = 0; l < 2; l++) {
                    int idx = tid + 256 * l;
                    int m = idx >> 2, k2 = (idx & 3) * 2;
                    As[nb][k2 + 0][m] = pack_h2(pa[l].x, pa[l].y);
                    As[nb][k2 + 1][m] = pack_h2(pa[l].z, pa[l].w);
                }
            }
            #pragma unroll
            for (int l = 0; l < 4; l++) {
                int idx = tid + 256 * l;
                Bs[nb][idx >> 7][idx & 127] = pb[l];
            }
        }
        __syncthreads();
    }
    #pragma unroll
    for (int mt = 0; mt < 4; mt++) {
        #pragma unroll
        for (int i = 0; i < 2; i++) {
            int r = row0 + wm + mt * 16 + gid + i * 8;
            #pragma unroll
            for (int nt = 0; nt < 4; nt++) {
                int cb = col0 + wn + nt * 8 + 2 * tig;
                float v0 = acc[mt][nt][i * 2 + 0] + Bias[cb + 0];
                float v1 = acc[mt][nt][i * 2 + 1] + Bias[cb + 1];
                if (MODE == 1) proj_store2(r, cb, v0, v1);
                else {
                    C[(size_t)r * N + cb]     = v0;
                    C[(size_t)r * N + cb + 1] = v1;
                }
            }
        }
    }
}

// ---------------- pipelined 128x64 fp16 edge GEMM ----------------
__device__ __forceinline__ void edge_gemm_f16(const float* __restrict__ A,
                                              const unsigned* __restrict__ W16,
                                              const float* __restrict__ Bias,
                                              const int* __restrict__ rowmap,
                                              int row0, char* smemraw) {
    unsigned (*As)[8][AP2] = reinterpret_cast<unsigned (*)[8][AP2]>(smemraw);
    unsigned (*Bs)[8][EBP2] = reinterpret_cast<unsigned (*)[8][EBP2]>(smemraw + 2 * 8 * AP2 * 4);
    const int tid = threadIdx.x;
    const int lane = tid & 31, w = tid >> 5;
    const int gid = lane >> 2, tig = lane & 3;
    const int wm = (w & 3) * 32;
    const int wn = (w >> 2) * 32;
    const int N = EDGE_COLS, K = CZ;

    float c[2][4][4];
    #pragma unroll
    for (int mt = 0; mt < 2; mt++)
        #pragma unroll
        for (int nt = 0; nt < 4; nt++)
            #pragma unroll
            for (int i = 0; i < 4; i++) c[mt][nt][i] = 0.f;

    float4 pa[2];
    unsigned pb[2];

    #pragma unroll
    for (int l = 0; l < 2; l++) {
        int idx = tid + 256 * l;
        int r = idx >> 2, kc = (idx & 3) * 4;
        pa[l] = *reinterpret_cast<const float4*>(&A[(size_t)(row0 + r) * K + kc]);
    }
    #pragma unroll
    for (int l = 0; l < 2; l++) {
        int idx = tid + 256 * l;
        int r = idx >> 6, cc = idx & 63;
        pb[l] = (cc < N) ? W16[(size_t)r * N + cc] : 0u;
    }
    #pragma unroll
    for (int l = 0; l < 2; l++) {
        int idx = tid + 256 * l;
        int r = idx >> 2, k2 = (idx & 3) * 2;
        As[0][k2 + 0][r] = pack_h2(pa[l].x, pa[l].y);
        As[0][k2 + 1][r] = pack_h2(pa[l].z, pa[l].w);
    }
    #pragma unroll
    for (int l = 0; l < 2; l++) {
        int idx = tid + 256 * l;
        Bs[0][idx >> 6][idx & 63] = pb[l];
    }
    __syncthreads();

    const int nIter = K / 16;
    for (int it = 0; it < nIter; it++) {
        int buf = it & 1;
        if (it + 1 < nIter) {
            int k0 = (it + 1) * 16;
            #pragma unroll
            for (int l = 0; l < 2; l++) {
                int idx = tid + 256 * l;
                int r = idx >> 2, kc = (idx & 3) * 4;
                pa[l] = *reinterpret_cast<const float4*>(&A[(size_t)(row0 + r) * K + k0 + kc]);
            }
            #pragma unroll
            for (int l = 0; l < 2; l++) {
                int idx = tid + 256 * l;
                int r = idx >> 6, cc = idx & 63;
                pb[l] = (cc < N) ? W16[(size_t)(k0 / 2 + r) * N + cc] : 0u;
            }
        }
        {
            unsigned a[2][4], b[4][2];
            #pragma unroll
            for (int mt = 0; mt < 2; mt++) {
                int m0 = wm + mt * 16;
                a[mt][0] = As[buf][tig][m0 + gid];
                a[mt][1] = As[buf][tig][m0 + gid + 8];
                a[mt][2] = As[buf][tig + 4][m0 + gid];
                a[mt][3] = As[buf][tig + 4][m0 + gid + 8];
            }
            #pragma unroll
            for (int nt = 0; nt < 4; nt++) {
                int n0 = wn + nt * 8;
                b[nt][0] = Bs[buf][tig][n0 + gid];
                b[nt][1] = Bs[buf][tig + 4][n0 + gid];
            }
            #pragma unroll
            for (int mt = 0; mt < 2; mt++)
                #pragma unroll
                for (int nt = 0; nt < 4; nt++)
                    mma_f16(c[mt][nt], a[mt][0], a[mt][1], a[mt][2], a[mt][3],
                            b[nt][0], b[nt][1]);
        }
        if (it + 1 < nIter) {
            int nb = 1 - buf;
            #pragma unroll
            for (int l = 0; l < 2; l++) {
                int idx = tid + 256 * l;
                int r = idx >> 2, k2 = (idx & 3) * 2;
                As[nb][k2 + 0][r] = pack_h2(pa[l].x, pa[l].y);
                As[nb][k2 + 1][r] = pack_h2(pa[l].z, pa[l].w);
            }
            #pragma unroll
            for (int l = 0; l < 2; l++) {
                int idx = tid + 256 * l;
                Bs[nb][idx >> 6][idx & 63] = pb[l];
            }
        }
        __syncthreads();
    }
    #pragma unroll
    for (int mt = 0; mt < 2; mt++) {
        #pragma unroll
        for (int i = 0; i < 2; i++) {
            int r = row0 + wm + mt * 16 + gid + i * 8;
            int crow = rowmap[r];
            #pragma unroll
            for (int nt = 0; nt < 4; nt++) {
                int cbase = wn + nt * 8 + 2 * tig;
                #pragma unroll
                for (int j = 0; j < 2; j++) {
                    int cc = cbase + j;
                    if (cc < N) {
                        float val = c[mt][nt][i * 2 + j] + Bias[cc];
                        if (cc < 12) g_bE[(size_t)crow * 12 + cc] = val;
                        else         g_pz16[(size_t)crow * 32 + (cc - 12)] = __float2half(val);
                    }
                }
            }
        }
    }
}

__global__ __launch_bounds__(256, 2) void k_gemm_proj(const float* __restrict__ s) {
    __shared__ __align__(16) char smemraw[SMEM_ARENA];
    int b = blockIdx.x;
    gemm128_f16<PROJ_COLS, CS, 1>(s, g_Wp16, g_Bproj, nullptr,
                                  (b / 9) * 128, (b % 9) * 128, smemraw);
}
__global__ __launch_bounds__(256, 2) void k_gemm_edge(const float* __restrict__ z) {
    __shared__ __align__(16) char smemraw[SMEM_ARENA];
    edge_gemm_f16(z, g_We16, g_Bedge, g_rank, blockIdx.x * 128, smemraw);
}
__global__ __launch_bounds__(256, 2) void k_gemm_out(const float* __restrict__ out_b,
                                                     float* __restrict__ out) {
    __shared__ __align__(16) char smemraw[SMEM_ARENA];
    gemm128_f16<CS, FEAT_COLS, 2>(g_feats16, g_Wo16, out_b, out,
                                  blockIdx.y * 128, blockIdx.x * 128, smemraw);
}

// ---------------- point transform ----------------
__global__ void k_pointify(const float* __restrict__ rot, const float* __restrict__ trans) {
    int gid = blockIdx.x * blockDim.x + threadIdx.x;
    if (gid >= NN * 192) return;
    int n = gid / 192;
    int p_all = gid % 192;
    const float* R = rot + (size_t)n * 9;
    const float* T = trans + (size_t)n * 3;
    const float* pr = g_proj + (size_t)n * PROJ_COLS;
    if (p_all < 48) {
        int p = p_all;
        float y0 = pr[576 + 0 * 48 + p];
        float y1 = pr[576 + 1 * 48 + p];
        float y2 = pr[576 + 2 * 48 + p];
        #pragma unroll
        for (int i = 0; i < 3; i++) {
            float v = R[i * 3 + 0] * y0 + R[i * 3 + 1] * y1 + R[i * 3 + 2] * y2 + T[i];
            g_qpts[((size_t)n * 48 + p) * 3 + i] = v;
        }
    } else {
        int p = p_all - 48;
        float y0 = pr[720 + 0 * 144 + p];
        float y1 = pr[720 + 1 * 144 + p];
        float y2 = pr[720 + 2 * 144 + p];
        int h = p / 12, j = p % 12;
        #pragma unroll
        for (int i = 0; i < 3; i++) {
            float v = R[i * 3 + 0] * y0 + R[i * 3 + 1] * y1 + R[i * 3 + 2] * y2 + T[i];
            if (j < PQK) g_kpts[((size_t)n * 48 + h * 4 + j) * 3 + i] = v;
            else         g_vpts16[(size_t)n * 288 + (h * 8 + (j - 4)) * 3 + i] = __float2half(v);
        }
    }
}

// ---------------- fused per-node: logits + softmax + aggregation ----------------
__device__ __forceinline__ float4 h4_to_f4(uint2 u) {
    __half2* hp = reinterpret_cast<__half2*>(&u);
    float2 f0 = __half22float2(hp[0]);
    float2 f1 = __half22float2(hp[1]);
    return make_float4(f0.x, f0.y, f1.x, f1.y);
}

template <bool FAST>
__device__ __forceinline__ void node_body(
    int n, int tid, int beg, int dn,
    const float* __restrict__ mask, const float* __restrict__ head_weights,
    const float* __restrict__ rot, const float* __restrict__ trans,
    float4* s_q, float4* s_qp, float* s_hw, float* s_logit, int* s_dst,
    float* s_red, float* s_amax, float* s_inv, float* sacc, float* s_pt2) {

    const float4* proj4 = reinterpret_cast<const float4*>(g_proj);
    const float4* kpts4 = reinterpret_cast<const float4*>(g_kpts);

    float* lb = FAST ? s_logit : (g_abuf + (size_t)beg * HH);
    const int* dl = FAST ? s_dst : (g_dstOf + beg);

    if (tid < 48) s_q[tid] = proj4[(size_t)n * 288 + tid];
    else if (tid < 84) s_qp[tid - 48] = reinterpret_cast<const float4*>(g_qpts)[(size_t)n * 36 + (tid - 48)];
    else if (tid < 96) s_hw[tid - 84] = 0.5f * S_PT * log1pf(expf(head_weights[tid - 84]));
    if (FAST) {
        for (int i = tid; i < dn; i += 256) s_dst[i] = g_dstOf[beg + i];
    }
    __syncthreads();

    float mn = mask[n];

    if (tid < 252) {
        int h = tid % HH;
        float4 q0 = s_q[h * 4 + 0], q1 = s_q[h * 4 + 1], q2 = s_q[h * 4 + 2], q3 = s_q[h * 4 + 3];
        float4 p0 = s_qp[h * 3 + 0], p1 = s_qp[h * 3 + 1], p2 = s_qp[h * 3 + 2];
        float hwv = s_hw[h];
        for (int i = tid / HH; i < dn; i += 21) {
            int dst = dl[i];
            const uint4* kh = reinterpret_cast<const uint4*>(g_k16 + (size_t)dst * 192 + h * 16);
            uint4 u0 = kh[0], u1 = kh[1];
            __half2* h0 = reinterpret_cast<__half2*>(&u0);
            __half2* h1 = reinterpret_cast<__half2*>(&u1);
            float2 f0 = __half22float2(h0[0]), f1 = __half22float2(h0[1]);
            float2 f2 = __half22float2(h0[2]), f3 = __half22float2(h0[3]);
            float2 f4 = __half22float2(h1[0]), f5 = __half22float2(h1[1]);
            float2 f6 = __half22float2(h1[2]), f7 = __half22float2(h1[3]);
            float dot = q0.x * f0.x + q0.y * f0.y + q0.z * f1.x + q0.w * f1.y
                      + q1.x * f2.x + q1.y * f2.y + q1.z * f3.x + q1.w * f3.y
                      + q2.x * f4.x + q2.y * f4.y + q2.z * f5.x + q2.w * f5.y
                      + q3.x * f6.x + q3.y * f6.y + q3.z * f7.x + q3.w * f7.y;
            const float4* kp = kpts4 + (size_t)dst * 36 + h * 3;
            float4 d0 = kp[0], d1 = kp[1], d2 = kp[2];
            float pt = 0.f;
            pt += (p0.x - d0.x) * (p0.x - d0.x) + (p0.y - d0.y) * (p0.y - d0.y)
                + (p0.z - d0.z) * (p0.z - d0.z) + (p0.w - d0.w) * (p0.w - d0.w);
            pt += (p1.x - d1.x) * (p1.x - d1.x) + (p1.y - d1.y) * (p1.y - d1.y)
                + (p1.z - d1.z) * (p1.z - d1.z) + (p1.w - d1.w) * (p1.w - d1.w);
            pt += (p2.x - d2.x) * (p2.x - d2.x) + (p2.y - d2.y) * (p2.y - d2.y)
                + (p2.z - d2.z) * (p2.z - d2.z) + (p2.w - d2.w) * (p2.w - d2.w);
            float b = g_bE[(size_t)(beg + i) * 12 + h];
            float em = INF_C * (mask[dst] * mn - 1.f);
            lb[i * HH + h] = dot * S_QK + S_B * b - hwv * pt + em;
        }
    }
    __syncthreads();

    if (tid < 96) {
        int h = tid % HH, j = tid / HH;
        float m = -INFINITY;
        for (int i = j; i < dn; i += 8) m = fmaxf(m, lb[i * HH + h]);
        s_red[tid] = m;
    }
    __syncthreads();
    if (tid < HH) {
        float m = -INFINITY;
        #pragma unroll
        for (int j = 0; j < 8; j++) m = fmaxf(m, s_red[j * HH + tid]);
        if (!isfinite(m)) m = 0.f;
        s_amax[tid] = m;
    }
    __syncthreads();
    // denominator pass: computes exp once and stores it back to lb
    if (tid < 96) {
        int h = tid % HH, j = tid / HH;
        float am = s_amax[h];
        float s = 0.f;
        for (int i = j; i < dn; i += 8) {
            float e = expf(lb[i * HH + h] - am);
            lb[i * HH + h] = e;
            s += e;
        }
        s_red[tid] = s;
    }
    __syncthreads();
    if (tid < HH) {
        float s = 0.f;
        #pragma unroll
        for (int j = 0; j < 8; j++) s += s_red[j * HH + tid];
        s_inv[tid] = 1.f / (s + 1e-16f);
    }
    __syncthreads();

    // normalize: pure multiply (exp already applied)
    for (int idx = tid; idx < dn * HH; idx += 256) {
        int h = idx % HH;
        lb[idx] *= s_inv[h];
    }
    __syncthreads();

    if (tid < 144) {
        int chunk = tid / 72;
        int c = tid % 72;
        int h = c / 6;
        float4 acc = {0.f, 0.f, 0.f, 0.f};
        #pragma unroll 8
        for (int i = chunk; i < dn; i += 2) {
            int dst = dl[i];
            float w = lb[i * HH + h];
            float4 v = h4_to_f4(*reinterpret_cast<const uint2*>(g_vpts16 + (size_t)dst * 288 + c * 4));
            acc.x += w * v.x; acc.y += w * v.y; acc.z += w * v.z; acc.w += w * v.w;
        }
        float* dstp = (chunk == 0) ? (sacc + 192 + c * 4) : (s_pt2 + c * 4);
        dstp[0] = acc.x; dstp[1] = acc.y; dstp[2] = acc.z; dstp[3] = acc.w;
    } else if (tid >= 160 && tid < 208) {
        int c = tid - 160;
        int h = c >> 2, c4 = c & 3;
        float4 acc = {0.f, 0.f, 0.f, 0.f};
        #pragma unroll 8
        for (int i = 0; i < dn; i++) {
            int dst = dl[i];
            float w = lb[i * HH + h];
            float4 v = h4_to_f4(*reinterpret_cast<const uint2*>(g_v16 + (size_t)dst * 192 + h * 16 + c4 * 4));
            acc.x += w * v.x; acc.y += w * v.y; acc.z += w * v.z; acc.w += w * v.w;
        }
        sacc[c * 4 + 0] = acc.x; sacc[c * 4 + 1] = acc.y;
        sacc[c * 4 + 2] = acc.z; sacc[c * 4 + 3] = acc.w;
    } else if (tid >= 224 && tid < 248) {
        int c = tid - 224;
        int j = c & 7, hq = c >> 3;
        float4 acc[4];
        #pragma unroll
        for (int r = 0; r < 4; r++) acc[r] = make_float4(0.f, 0.f, 0.f, 0.f);
        #pragma unroll 8
        for (int i = 0; i < dn; i++) {
            float4 p = h4_to_f4(*reinterpret_cast<const uint2*>(g_pz16 + (size_t)(beg + i) * 32 + j * 4));
            #pragma unroll
            for (int r = 0; r < 4; r++) {
                float w = lb[i * HH + hq * 4 + r];
                acc[r].x += w * p.x; acc[r].y += w * p.y;
                acc[r].z += w * p.z; acc[r].w += w * p.w;
            }
        }
        #pragma unroll
        for (int r = 0; r < 4; r++) {
            int base = 480 + (hq * 4 + r) * 32 + j * 4;
            sacc[base + 0] = acc[r].x; sacc[base + 1] = acc[r].y;
            sacc[base + 2] = acc[r].z; sacc[base + 3] = acc[r].w;
        }
    }
    __syncthreads();
    for (int t = tid; t < 288; t += 256) sacc[192 + t] += s_pt2[t];
    __syncthreads();

    __half* f = g_feats16 + (size_t)n * FEAT_COLS;
    if (tid < 192) f[tid] = __float2half(sacc[tid]);
    for (int t = tid; t < 384; t += 256) f[576 + t] = __float2half(sacc[480 + t]);
    if (tid < 96) {
        int q = tid;
        float g0 = sacc[192 + q * 3 + 0] - trans[(size_t)n * 3 + 0];
        float g1 = sacc[192 + q * 3 + 1] - trans[(size_t)n * 3 + 1];
        float g2 = sacc[192 + q * 3 + 2] - trans[(size_t)n * 3 + 2];
        const float* R = rot + (size_t)n * 9;
        float l0 = R[0] * g0 + R[3] * g1 + R[6] * g2;
        float l1 = R[1] * g0 + R[4] * g1 + R[7] * g2;
        float l2 = R[2] * g0 + R[5] * g1 + R[8] * g2;
        f[192 + q] = __float2half(l0);
        f[288 + q] = __float2half(l1);
        f[384 + q] = __float2half(l2);
        f[480 + q] = __float2half(sqrtf(l0 * l0 + l1 * l1 + l2 * l2 + 1e-8f));
    }
}

__global__ void k_node(const float* __restrict__ mask, const float* __restrict__ head_weights,
                       const float* __restrict__ rot, const float* __restrict__ trans) {
    __shared__ float4 s_q[48];
    __shared__ float4 s_qp[36];
    __shared__ float  s_hw[12];
    __shared__ float  s_logit[DN_FAST * HH];
    __shared__ int    s_dst[DN_FAST];
    __shared__ float  s_red[96];
    __shared__ float  s_amax[HH], s_inv[HH];
    __shared__ float  sacc[864];
    __shared__ float  s_pt2[288];

    int n = blockIdx.x;
    int tid = threadIdx.x;
    int beg = g_off[n], dn = g_off[n + 1] - beg;

    if (dn <= DN_FAST)
        node_body<true>(n, tid, beg, dn, mask, head_weights, rot, trans,
                        s_q, s_qp, s_hw, s_logit, s_dst, s_red, s_amax, s_inv, sacc, s_pt2);
    else
        node_body<false>(n, tid, beg, dn, mask, head_weights, rot, trans,
                         s_q, s_qp, s_hw, s_logit, s_dst, s_red, s_amax, s_inv, sacc, s_pt2);
}

// ---------------- launch ----------------
extern "C" void kernel_launch(void* const* d_in, const int* in_sizes, int n_in,
                              void* d_out, int out_size) {
    const float* s          = (const float*)d_in[0];
    const float* z          = (const float*)d_in[1];
    const int*   edge_index = (const int*)  d_in[2];
    const float* rot        = (const float*)d_in[3];
    const float* trans      = (const float*)d_in[4];
    const float* mask       = (const float*)d_in[5];
    const float* q_w        = (const float*)d_in[6];
    const float* q_b        = (const float*)d_in[7];
    const float* kv_w       = (const float*)d_in[8];
    const float* kv_b       = (const float*)d_in[9];
    const float* qp_w       = (const float*)d_in[10];
    const float* qp_b       = (const float*)d_in[11];
    const float* kvp_w      = (const float*)d_in[12];
    const float* kvp_b      = (const float*)d_in[13];
    const float* b_w        = (const float*)d_in[14];
    const float* b_b        = (const float*)d_in[15];
    const float* dz_w       = (const float*)d_in[16];
    const float* dz_b       = (const float*)d_in[17];
    const float* head_w     = (const float*)d_in[18];
    const float* out_w      = (const float*)d_in[19];
    const float* out_b      = (const float*)d_in[20];
    float* out = (float*)d_out;

    static cudaStream_t s2;
    static cudaEvent_t ev0, ev2;
    static int inited = 0;
    static bool streamsOK = false;
    if (!inited) {
        inited = 1;
        streamsOK =
            cudaStreamCreateWithFlags(&s2, cudaStreamNonBlocking) == cudaSuccess &&
            cudaEventCreateWithFlags(&ev0, cudaEventDisableTiming) == cudaSuccess &&
            cudaEventCreateWithFlags(&ev2, cudaEventDisableTiming) == cudaSuccess;
    }

    if (streamsOK) {
        cudaEventRecord(ev0, 0);
        cudaStreamWaitEvent(s2, ev0, 0);
        k_zero_hist<<<NN / 256, 256, 0, s2>>>();
        k_hist<<<NE / 256, 256, 0, s2>>>(edge_index);
        k_scan<<<1, 1024, 0, s2>>>();
        k_scatter<<<NE / 256, 256, 0, s2>>>(edge_index);
        k_pack_rest<<<(PACKR_TOTAL + 255) / 256, 256, 0, s2>>>(b_w, b_b, dz_w, dz_b, out_w);
        k_gemm_edge<<<NE / 128, 256, 0, s2>>>(z);
        cudaEventRecord(ev2, s2);

        k_pack_proj<<<(PACKP_TOTAL + 255) / 256, 256>>>(q_w, q_b, kv_w, kv_b,
                                                        qp_w, qp_b, kvp_w, kvp_b);
        k_gemm_proj<<<(PROJ_COLS / 128) * (NN / 128), 256>>>(s);
        k_pointify<<<(NN * 192) / 256, 256>>>(rot, trans);

        cudaStreamWaitEvent(0, ev2, 0);
        k_node<<<NN, 256>>>(mask, head_w, rot, trans);
        k_gemm_out<<<dim3(CS / 128, NN / 128), 256>>>(out_b, out);
    } else {
        k_pack_proj<<<(PACKP_TOTAL + 255) / 256, 256>>>(q_w, q_b, kv_w, kv_b,
                                                        qp_w, qp_b, kvp_w, kvp_b);
        k_pack_rest<<<(PACKR_TOTAL + 255) / 256, 256>>>(b_w, b_b, dz_w, dz_b, out_w);
        k_zero_hist<<<NN / 256, 256>>>();
        k_hist<<<NE / 256, 256>>>(edge_index);
        k_scan<<<1, 1024>>>();
        k_scatter<<<NE / 256, 256>>>(edge_index);
        k_gemm_edge<<<NE / 128, 256>>>(z);
        k_gemm_proj<<<(PROJ_COLS / 128) * (NN / 128), 256>>>(s);
        k_pointify<<<(NN * 192) / 256, 256>>>(rot, trans);
        k_node<<<NN, 256>>>(mask, head_w, rot, trans);
        k_gemm_out<<<dim3(CS / 128, NN / 128), 256>>>(out_b, out);
    }
}